// round 2
// baseline (speedup 1.0000x reference)
#include <cuda_runtime.h>
#include <math.h>

// Problem constants
constexpr int B  = 2;
constexpr int S  = 2048;
constexpr int D  = 1024;
constexpr int H  = 16;
constexpr int HD = 64;
constexpr int M  = B * S;       // 4096 rows for projection GEMMs
constexpr int BH = B * H;       // 32

// Scratch (allocation-free rule: __device__ globals; referenced directly by
// device code — no cudaGetSymbolAddress anywhere)
__device__ float g_Q[B * H * S * HD];   // 16 MB, head layout [b,h,s,hd]
__device__ float g_K[B * H * S * HD];
__device__ float g_V[B * H * S * HD];
__device__ float g_att[B * S * D];      // attention output, flat [b,s,d]

// ---------------------------------------------------------------------------
// GEMM: C = X @ W^T.  X:[M,1024] row-major, W:[1024,1024] row-major (out,in).
// 128x64 tile per CTA, BK=16, 256 threads, 8x4 microtile per thread.
// mode: 1/2/3 -> write head-layout [b,h,s,hd] into g_Q/g_K/g_V
//       0     -> write flat [M,D] into Out
//       4     -> read X from g_att, write flat into Out
// ---------------------------------------------------------------------------
__global__ __launch_bounds__(256)
void gemm128(const float* __restrict__ X, const float* __restrict__ W,
             float* __restrict__ Out, float scale, int mode)
{
    __shared__ float As[16][132];   // k-major, 128 rows + pad4 (16B-aligned frags)
    __shared__ float Bs[16][68];    // k-major, 64 rows + pad4

    const int tid = threadIdx.x;
    const int tx  = tid & 15;       // 0..15 -> N (cols tx*4)
    const int ty  = tid >> 4;       // 0..15 -> M (rows ty*8)
    const int row0 = blockIdx.y * 128;
    const int col0 = blockIdx.x * 64;

    const float* Xbase = (mode == 4) ? g_att : X;

    // A loader: thread -> row ar (0..127), k-offset ak in {0,8}, two float4
    const int ar = tid >> 1;
    const int ak = (tid & 1) * 8;
    // B loader: thread -> row br (0..63), k-offset bk in {0,4,8,12}, one float4
    const int br = tid >> 2;
    const int bk = (tid & 3) * 4;

    const float* Xp = Xbase + (size_t)(row0 + ar) * D;
    const float* Wp = W     + (size_t)(col0 + br) * D;

    float acc[8][4] = {};

    for (int kt = 0; kt < D; kt += 16) {
        float4 xa0 = *(const float4*)(Xp + kt + ak);
        float4 xa1 = *(const float4*)(Xp + kt + ak + 4);
        float4 wb  = *(const float4*)(Wp + kt + bk);
        As[ak + 0][ar] = xa0.x; As[ak + 1][ar] = xa0.y;
        As[ak + 2][ar] = xa0.z; As[ak + 3][ar] = xa0.w;
        As[ak + 4][ar] = xa1.x; As[ak + 5][ar] = xa1.y;
        As[ak + 6][ar] = xa1.z; As[ak + 7][ar] = xa1.w;
        Bs[bk + 0][br] = wb.x;  Bs[bk + 1][br] = wb.y;
        Bs[bk + 2][br] = wb.z;  Bs[bk + 3][br] = wb.w;
        __syncthreads();

        #pragma unroll
        for (int k = 0; k < 16; k++) {
            float4 a0 = *(const float4*)&As[k][ty * 8];
            float4 a1 = *(const float4*)&As[k][ty * 8 + 4];
            float4 b4 = *(const float4*)&Bs[k][tx * 4];
            float a[8] = {a0.x, a0.y, a0.z, a0.w, a1.x, a1.y, a1.z, a1.w};
            float b[4] = {b4.x, b4.y, b4.z, b4.w};
            #pragma unroll
            for (int i = 0; i < 8; i++)
                #pragma unroll
                for (int j = 0; j < 4; j++)
                    acc[i][j] = fmaf(a[i], b[j], acc[i][j]);
        }
        __syncthreads();
    }

    if (mode == 0 || mode == 4) {
        #pragma unroll
        for (int i = 0; i < 8; i++) {
            float4 o = make_float4(acc[i][0] * scale, acc[i][1] * scale,
                                   acc[i][2] * scale, acc[i][3] * scale);
            *(float4*)&Out[(size_t)(row0 + ty * 8 + i) * D + col0 + tx * 4] = o;
        }
    } else {
        float* dst = (mode == 1) ? g_Q : (mode == 2) ? g_K : g_V;
        const int h = col0 >> 6;              // this 64-wide col tile == one head
        #pragma unroll
        for (int i = 0; i < 8; i++) {
            const int gr = row0 + ty * 8 + i;
            const int b  = gr >> 11;          // / S
            const int s  = gr & (S - 1);
            float4 o = make_float4(acc[i][0] * scale, acc[i][1] * scale,
                                   acc[i][2] * scale, acc[i][3] * scale);
            *(float4*)&dst[(((size_t)(b * H + h) * S) + s) * HD + tx * 4] = o;
        }
    }
}

// ---------------------------------------------------------------------------
// Flash attention, causal. One CTA = one (b,h) x 64-row q tile.
// 256 threads; score/PV microtiles are 4x4 with rows ty+16i, cols tx+16j so
// all smem fragment loads are broadcast or stride-1 (stride-65 rows).
// ---------------------------------------------------------------------------
constexpr int ATT_SMEM = 4 * 64 * 65 * (int)sizeof(float);   // 66560 B

__global__ __launch_bounds__(256)
void attn64()
{
    extern __shared__ float sm[];
    float* Qs = sm;                // [64][65]
    float* Ks = Qs + 64 * 65;
    float* Vs = Ks + 64 * 65;
    float* Ps = Vs + 64 * 65;

    const int tid = threadIdx.x;
    const int tx  = tid & 15;
    const int ty  = tid >> 4;
    const int qt  = (int)(gridDim.x - 1 - blockIdx.x);  // heavy tiles first
    const int bh  = blockIdx.y;           // 0..31
    const int q0  = qt * 64;

    const float* Qp = g_Q + (size_t)bh * S * HD;
    const float* Kp = g_K + (size_t)bh * S * HD;
    const float* Vp = g_V + (size_t)bh * S * HD;

    // tile loader: 64x64 floats, 16 per thread
    const int lr = tid >> 2;              // 0..63
    const int lc = (tid & 3) * 4;         // 0,4,8,12

    {   // Q tile (loaded once)
        const float* src = Qp + (size_t)(q0 + lr) * HD;
        #pragma unroll
        for (int u = 0; u < 4; u++) {
            float4 v = *(const float4*)(src + lc + u * 16);
            float* d = &Qs[lr * 65 + lc + u * 16];
            d[0] = v.x; d[1] = v.y; d[2] = v.z; d[3] = v.w;
        }
    }

    float acc[4][4] = {};
    float mrow[4], lrow[4];
    #pragma unroll
    for (int i = 0; i < 4; i++) { mrow[i] = -1e30f; lrow[i] = 0.f; }

    for (int kt = 0; kt <= qt; kt++) {
        __syncthreads();   // previous PV done with Vs/Ps before overwrite
        const int k0 = kt * 64;
        {
            const float* srcK = Kp + (size_t)(k0 + lr) * HD;
            const float* srcV = Vp + (size_t)(k0 + lr) * HD;
            #pragma unroll
            for (int u = 0; u < 4; u++) {
                float4 vk = *(const float4*)(srcK + lc + u * 16);
                float4 vv = *(const float4*)(srcV + lc + u * 16);
                float* dk = &Ks[lr * 65 + lc + u * 16];
                float* dv = &Vs[lr * 65 + lc + u * 16];
                dk[0] = vk.x; dk[1] = vk.y; dk[2] = vk.z; dk[3] = vk.w;
                dv[0] = vv.x; dv[1] = vv.y; dv[2] = vv.z; dv[3] = vv.w;
            }
        }
        __syncthreads();

        // scores: S = Q (pre-scaled) . K^T
        float sc[4][4] = {};
        #pragma unroll 16
        for (int d = 0; d < 64; d++) {
            float a[4], b[4];
            #pragma unroll
            for (int i = 0; i < 4; i++) a[i] = Qs[(ty + 16 * i) * 65 + d];
            #pragma unroll
            for (int j = 0; j < 4; j++) b[j] = Ks[(tx + 16 * j) * 65 + d];
            #pragma unroll
            for (int i = 0; i < 4; i++)
                #pragma unroll
                for (int j = 0; j < 4; j++)
                    sc[i][j] = fmaf(a[i], b[j], sc[i][j]);
        }

        if (kt == qt) {   // diagonal tile: causal mask (q0 == k0)
            #pragma unroll
            for (int i = 0; i < 4; i++)
                #pragma unroll
                for (int j = 0; j < 4; j++)
                    if ((tx + 16 * j) > (ty + 16 * i)) sc[i][j] = -1e30f;
        }

        // online softmax update (row reduce over the 16 tx lanes)
        #pragma unroll
        for (int i = 0; i < 4; i++) {
            float m = fmaxf(fmaxf(sc[i][0], sc[i][1]), fmaxf(sc[i][2], sc[i][3]));
            #pragma unroll
            for (int o = 8; o >= 1; o >>= 1)
                m = fmaxf(m, __shfl_xor_sync(0xffffffffu, m, o));
            const float mn   = fmaxf(mrow[i], m);
            const float corr = __expf(mrow[i] - mn);
            float rs = 0.f;
            #pragma unroll
            for (int j = 0; j < 4; j++) {
                sc[i][j] = __expf(sc[i][j] - mn);
                rs += sc[i][j];
            }
            #pragma unroll
            for (int o = 8; o >= 1; o >>= 1)
                rs += __shfl_xor_sync(0xffffffffu, rs, o);
            lrow[i] = lrow[i] * corr + rs;
            mrow[i] = mn;
            #pragma unroll
            for (int j = 0; j < 4; j++) {
                acc[i][j] *= corr;
                Ps[(ty + 16 * i) * 65 + tx + 16 * j] = sc[i][j];
            }
        }
        __syncthreads();

        // O += P . V
        #pragma unroll 16
        for (int kk = 0; kk < 64; kk++) {
            float a[4], b[4];
            #pragma unroll
            for (int i = 0; i < 4; i++) a[i] = Ps[(ty + 16 * i) * 65 + kk];
            #pragma unroll
            for (int j = 0; j < 4; j++) b[j] = Vs[kk * 65 + tx + 16 * j];
            #pragma unroll
            for (int i = 0; i < 4; i++)
                #pragma unroll
                for (int j = 0; j < 4; j++)
                    acc[i][j] = fmaf(a[i], b[j], acc[i][j]);
        }
    }

    // epilogue: normalize, write flat [b, s, h*64+hd]
    const int b = bh / H, h = bh % H;
    #pragma unroll
    for (int i = 0; i < 4; i++) {
        const int q  = q0 + ty + 16 * i;
        const float inv = 1.f / lrow[i];
        float* dst = g_att + ((size_t)b * S + q) * D + h * HD + tx;
        #pragma unroll
        for (int j = 0; j < 4; j++)
            dst[16 * j] = acc[i][j] * inv;
    }
}

// ---------------------------------------------------------------------------
extern "C" void kernel_launch(void* const* d_in, const int* in_sizes, int n_in,
                              void* d_out, int out_size)
{
    const float* q  = (const float*)d_in[0];
    const float* k  = (const float*)d_in[1];
    const float* v  = (const float*)d_in[2];
    const float* wq = (const float*)d_in[3];
    const float* wk = (const float*)d_in[4];
    const float* wv = (const float*)d_in[5];
    const float* wo = (const float*)d_in[6];
    float* out = (float*)d_out;

    cudaFuncSetAttribute(attn64, cudaFuncAttributeMaxDynamicSharedMemorySize,
                         ATT_SMEM);

    dim3 gblk(256);
    dim3 ggrid(D / 64, M / 128);           // (16, 32)

    const float qscale = 0.125f;           // 1/sqrt(64)
    gemm128<<<ggrid, gblk>>>(q, wq, nullptr, qscale, 1);
    gemm128<<<ggrid, gblk>>>(k, wk, nullptr, 1.0f,  2);
    gemm128<<<ggrid, gblk>>>(v, wv, nullptr, 1.0f,  3);

    dim3 agrid(S / 64, BH);                // (32, 32)
    attn64<<<agrid, gblk, ATT_SMEM>>>();

    gemm128<<<ggrid, gblk>>>(nullptr, wo, out, 1.0f, 4);
}

// round 7
// speedup vs baseline: 1.7434x; 1.7434x over previous
#include <cuda_runtime.h>
#include <cuda_bf16.h>
#include <math.h>
#include <stdint.h>

// Problem constants
constexpr int B  = 2;
constexpr int S  = 2048;
constexpr int D  = 1024;
constexpr int H  = 16;
constexpr int HD = 64;
constexpr int M  = B * S;       // 4096
constexpr int BH = B * H;       // 32

// ---------------------------------------------------------------------------
// Scratch (__device__ globals)
// ---------------------------------------------------------------------------
__device__ float g_Q[B * H * S * HD];
__device__ float g_K[B * H * S * HD];
__device__ float g_V[B * H * S * HD];
__device__ float g_att[B * S * D];
__device__ __nv_bfloat16 g_Xh[M * D];
__device__ __nv_bfloat16 g_Xl[M * D];
__device__ __nv_bfloat16 g_Wh[D * D];
__device__ __nv_bfloat16 g_Wl[D * D];

// ---------------------------------------------------------------------------
// mma.sync helpers (sm_80+ PTX — valid on target sm_100)
// ---------------------------------------------------------------------------
__device__ __forceinline__ uint32_t smem_u32(const void* p) {
    uint32_t a;
    asm("{ .reg .u64 t; cvta.to.shared.u64 t, %1; cvt.u32.u64 %0, t; }"
        : "=r"(a) : "l"(p));
    return a;
}

__device__ __forceinline__ void ldmx4(uint32_t* r, uint32_t addr) {
    asm volatile("ldmatrix.sync.aligned.m8n8.x4.shared.b16 {%0,%1,%2,%3}, [%4];"
                 : "=r"(r[0]), "=r"(r[1]), "=r"(r[2]), "=r"(r[3]) : "r"(addr));
}

__device__ __forceinline__ void mma16816(float* d, const uint32_t* a,
                                         const uint32_t* b) {
    asm volatile(
        "mma.sync.aligned.m16n8k16.row.col.f32.bf16.bf16.f32 "
        "{%0,%1,%2,%3}, {%4,%5,%6,%7}, {%8,%9}, {%0,%1,%2,%3};"
        : "+f"(d[0]), "+f"(d[1]), "+f"(d[2]), "+f"(d[3])
        : "r"(a[0]), "r"(a[1]), "r"(a[2]), "r"(a[3]), "r"(b[0]), "r"(b[1]));
}

// ---------------------------------------------------------------------------
// fp32 -> bf16 hi/lo split. hi = truncate mantissa (exact bf16), lo = rn(x-hi).
// srcsel: 0 -> x param, 1 -> g_att. dstsel: 0 -> g_X{h,l}, 1 -> g_W{h,l}
// ---------------------------------------------------------------------------
__global__ __launch_bounds__(256)
void cvt_split(const float4* __restrict__ x, int dstsel, int srcsel, int nvec)
{
    int i = blockIdx.x * blockDim.x + threadIdx.x;
    if (i >= nvec) return;
    const float4* src = srcsel ? (const float4*)g_att : x;
    uint2* hi = dstsel ? (uint2*)g_Wh : (uint2*)g_Xh;
    uint2* lo = dstsel ? (uint2*)g_Wl : (uint2*)g_Xl;

    float4 v = src[i];
    uint32_t ux = __float_as_uint(v.x), uy = __float_as_uint(v.y);
    uint32_t uz = __float_as_uint(v.z), uw = __float_as_uint(v.w);
    float hx = __uint_as_float(ux & 0xFFFF0000u);
    float hy = __uint_as_float(uy & 0xFFFF0000u);
    float hz = __uint_as_float(uz & 0xFFFF0000u);
    float hw = __uint_as_float(uw & 0xFFFF0000u);
    uint2 h;
    h.x = __byte_perm(ux, uy, 0x7632);
    h.y = __byte_perm(uz, uw, 0x7632);
    __nv_bfloat162 l0 = __float22bfloat162_rn(make_float2(v.x - hx, v.y - hy));
    __nv_bfloat162 l1 = __float22bfloat162_rn(make_float2(v.z - hz, v.w - hw));
    uint2 lv;
    lv.x = *reinterpret_cast<uint32_t*>(&l0);
    lv.y = *reinterpret_cast<uint32_t*>(&l1);
    hi[i] = h;
    lo[i] = lv;
}

// ---------------------------------------------------------------------------
// mma.sync GEMM: C[row,col] = sum_k X[row,k] * W[col,k]   (X @ W^T)
// 128x128 CTA tile, 8 warps of 64x32, K-chunks of 64, double-buffered smem.
// Split: XhWh + XhWl + XlWh (3 mma per logical mma).
// Smem tiles: 128 rows x 72 halves (144B rows: +4-bank stagger, ldmatrix
// conflict-free). mode: 1/2/3 -> head layout g_Q/g_K/g_V ; 0 -> flat Out.
// ---------------------------------------------------------------------------
constexpr int TROWB  = 144;                 // tile row bytes (64 data + 8 pad halves)
constexpr int TILE_B = 128 * TROWB;         // 18432 B per tile
constexpr int BUF_B  = 4 * TILE_B;          // Ah,Al,Bh,Bl
constexpr int GEMM_SMEM = 2 * BUF_B;        // 147456 B

__global__ __launch_bounds__(256, 1)
void gemm_mma(float* __restrict__ Out, float scale, int mode)
{
    extern __shared__ __align__(128) char smem[];
    const uint32_t sb = smem_u32(smem);
    const int tid  = threadIdx.x;
    const int lane = tid & 31;
    const int wid  = tid >> 5;
    const int wm   = wid >> 2;             // 0..1  -> m offset wm*64
    const int wn   = wid & 3;              // 0..3  -> n offset wn*32
    const int col0 = blockIdx.x * 128;
    const int row0 = blockIdx.y * 128;

    const __nv_bfloat16* srcs[4] = {
        g_Xh + (size_t)row0 * D, g_Xl + (size_t)row0 * D,
        g_Wh + (size_t)col0 * D, g_Wl + (size_t)col0 * D };

    // chunk loader: per tile 128 rows x 128B; 8 uint4 per row; 4 uint4/thread
    auto load_chunk = [&](int kt, int buf) {
        char* bs = smem + buf * BUF_B;
        const int kbytes = kt * 128;       // 64 halves per chunk
        #pragma unroll
        for (int t = 0; t < 4; t++) {
            const char* g = (const char*)srcs[t] + kbytes;
            char* sd = bs + t * TILE_B;
            #pragma unroll
            for (int p = 0; p < 4; p++) {
                int u = tid + p * 256;
                int r = u >> 3, c16 = (u & 7) * 16;
                uint4 v = *(const uint4*)(g + (size_t)r * 2048 + c16);
                *(uint4*)(sd + r * TROWB + c16) = v;
            }
        }
    };

    float c[4][4][4] = {};   // [mtile][ntile][frag]

    load_chunk(0, 0);
    __syncthreads();

    for (int kt = 0; kt < 16; kt++) {
        const int buf = kt & 1;
        if (kt < 15) load_chunk(kt + 1, buf ^ 1);

        const uint32_t base = sb + buf * BUF_B;
        #pragma unroll
        for (int ks = 0; ks < 4; ks++) {
            const int k0 = ks * 16;
            // A fragments (hi & lo): row = wm*64 + i*16 + (lane&15),
            // col halves = k0 + (lane>>4)*8
            uint32_t ah[4][4], al[4][4];
            {
                const uint32_t rofs = (uint32_t)(wm * 64 + (lane & 15)) * TROWB
                                    + (uint32_t)(k0 + (lane >> 4) * 8) * 2;
                #pragma unroll
                for (int i = 0; i < 4; i++) {
                    ldmx4(ah[i], base + 0 * TILE_B + rofs + i * 16 * TROWB);
                    ldmx4(al[i], base + 1 * TILE_B + rofs + i * 16 * TROWB);
                }
            }
            // B fragments, two n8 tiles per ldmatrix.x4:
            // lanes 0-15 -> k0/k0+8 of n rows 0-7, lanes 16-31 -> n rows 8-15
            uint32_t bh[4][2], bl[4][2];
            {
                const uint32_t rpart = (uint32_t)(wn * 32 + (lane >> 4) * 8
                                                  + (lane & 7)) * TROWB
                                     + (uint32_t)(k0 + ((lane >> 3) & 1) * 8) * 2;
                #pragma unroll
                for (int pr = 0; pr < 2; pr++) {
                    uint32_t r4[4];
                    ldmx4(r4, base + 2 * TILE_B + rpart + pr * 16 * TROWB);
                    bh[pr * 2 + 0][0] = r4[0]; bh[pr * 2 + 0][1] = r4[1];
                    bh[pr * 2 + 1][0] = r4[2]; bh[pr * 2 + 1][1] = r4[3];
                    ldmx4(r4, base + 3 * TILE_B + rpart + pr * 16 * TROWB);
                    bl[pr * 2 + 0][0] = r4[0]; bl[pr * 2 + 0][1] = r4[1];
                    bl[pr * 2 + 1][0] = r4[2]; bl[pr * 2 + 1][1] = r4[3];
                }
            }
            #pragma unroll
            for (int i = 0; i < 4; i++)
                #pragma unroll
                for (int j = 0; j < 4; j++) {
                    mma16816(c[i][j], ah[i], bh[j]);
                    mma16816(c[i][j], ah[i], bl[j]);
                    mma16816(c[i][j], al[i], bh[j]);
                }
        }
        __syncthreads();
    }

    // Epilogue: thread owns rows (g, g+8) per m-tile, cols (2t, 2t+1) per n-tile
    const int g = lane >> 2, t2 = (lane & 3) * 2;
    #pragma unroll
    for (int i = 0; i < 4; i++) {
        #pragma unroll
        for (int half = 0; half < 2; half++) {
            const int gr = row0 + wm * 64 + i * 16 + g + half * 8;
            #pragma unroll
            for (int j = 0; j < 4; j++) {
                const int gc = col0 + wn * 32 + j * 8 + t2;
                float2 o = make_float2(c[i][j][half * 2 + 0] * scale,
                                       c[i][j][half * 2 + 1] * scale);
                if (mode == 0) {
                    *(float2*)&Out[(size_t)gr * D + gc] = o;
                } else {
                    float* basep = (mode == 1) ? g_Q : (mode == 2) ? g_K : g_V;
                    const int b = gr >> 11, s = gr & (S - 1);
                    const int h = gc >> 6, hd = gc & 63;
                    *(float2*)&basep[(((size_t)(b * H + h) * S) + s) * HD + hd] = o;
                }
            }
        }
    }
}

// ---------------------------------------------------------------------------
// Flash attention, causal. Vectorized LDS (float4 over d/kk), V transposed.
// ---------------------------------------------------------------------------
constexpr int ATT_SMEM = 4 * 64 * 68 * (int)sizeof(float);   // 69632 B

__global__ __launch_bounds__(256)
void attn64()
{
    extern __shared__ float sm[];
    float* Qs = sm;                // [64][68]
    float* Ks = Qs + 64 * 68;
    float* Vt = Ks + 64 * 68;      // transposed [hd][seq]
    float* Ps = Vt + 64 * 68;

    const int tid = threadIdx.x;
    const int tx  = tid & 15;
    const int ty  = tid >> 4;
    const int qt  = (int)(gridDim.x - 1 - blockIdx.x);  // heavy tiles first
    const int bh  = blockIdx.y;
    const int q0  = qt * 64;

    const float* Qp = g_Q + (size_t)bh * S * HD;
    const float* Kp = g_K + (size_t)bh * S * HD;
    const float* Vp = g_V + (size_t)bh * S * HD;

    const int lr = tid >> 2;
    const int lc = (tid & 3) * 4;

    {   // Q tile (once)
        const float* src = Qp + (size_t)(q0 + lr) * HD;
        #pragma unroll
        for (int u = 0; u < 4; u++) {
            float4 v = *(const float4*)(src + lc + u * 16);
            float* d = &Qs[lr * 68 + lc + u * 16];
            d[0] = v.x; d[1] = v.y; d[2] = v.z; d[3] = v.w;
        }
    }

    float acc[4][4] = {};
    float mrow[4], lrow[4];
    #pragma unroll
    for (int i = 0; i < 4; i++) { mrow[i] = -1e30f; lrow[i] = 0.f; }

    for (int kt = 0; kt <= qt; kt++) {
        __syncthreads();
        const int k0 = kt * 64;
        {
            const float* srcK = Kp + (size_t)(k0 + lr) * HD;
            const float* srcV = Vp + (size_t)(k0 + lr) * HD;
            #pragma unroll
            for (int u = 0; u < 4; u++) {
                float4 vk = *(const float4*)(srcK + lc + u * 16);
                float4 vv = *(const float4*)(srcV + lc + u * 16);
                float* dk = &Ks[lr * 68 + lc + u * 16];
                dk[0] = vk.x; dk[1] = vk.y; dk[2] = vk.z; dk[3] = vk.w;
                const int cc = lc + u * 16;
                Vt[(cc + 0) * 68 + lr] = vv.x;
                Vt[(cc + 1) * 68 + lr] = vv.y;
                Vt[(cc + 2) * 68 + lr] = vv.z;
                Vt[(cc + 3) * 68 + lr] = vv.w;
            }
        }
        __syncthreads();

        float sc[4][4] = {};
        #pragma unroll 4
        for (int d = 0; d < 64; d += 4) {
            float4 a4[4], b4[4];
            #pragma unroll
            for (int i = 0; i < 4; i++) a4[i] = *(const float4*)&Qs[(ty + 16 * i) * 68 + d];
            #pragma unroll
            for (int j = 0; j < 4; j++) b4[j] = *(const float4*)&Ks[(tx + 16 * j) * 68 + d];
            #pragma unroll
            for (int i = 0; i < 4; i++)
                #pragma unroll
                for (int j = 0; j < 4; j++) {
                    sc[i][j] = fmaf(a4[i].x, b4[j].x, sc[i][j]);
                    sc[i][j] = fmaf(a4[i].y, b4[j].y, sc[i][j]);
                    sc[i][j] = fmaf(a4[i].z, b4[j].z, sc[i][j]);
                    sc[i][j] = fmaf(a4[i].w, b4[j].w, sc[i][j]);
                }
        }

        if (kt == qt) {
            #pragma unroll
            for (int i = 0; i < 4; i++)
                #pragma unroll
                for (int j = 0; j < 4; j++)
                    if ((tx + 16 * j) > (ty + 16 * i)) sc[i][j] = -1e30f;
        }

        #pragma unroll
        for (int i = 0; i < 4; i++) {
            float m = fmaxf(fmaxf(sc[i][0], sc[i][1]), fmaxf(sc[i][2], sc[i][3]));
            #pragma unroll
            for (int o = 8; o >= 1; o >>= 1)
                m = fmaxf(m, __shfl_xor_sync(0xffffffffu, m, o));
            const float mn   = fmaxf(mrow[i], m);
            const float corr = __expf(mrow[i] - mn);
            float rs = 0.f;
            #pragma unroll
            for (int j = 0; j < 4; j++) {
                sc[i][j] = __expf(sc[i][j] - mn);
                rs += sc[i][j];
            }
            #pragma unroll
            for (int o = 8; o >= 1; o >>= 1)
                rs += __shfl_xor_sync(0xffffffffu, rs, o);
            lrow[i] = lrow[i] * corr + rs;
            mrow[i] = mn;
            #pragma unroll
            for (int j = 0; j < 4; j++) {
                acc[i][j] *= corr;
                Ps[(ty + 16 * i) * 68 + tx + 16 * j] = sc[i][j];
            }
        }
        __syncthreads();

        #pragma unroll 4
        for (int kk = 0; kk < 64; kk += 4) {
            float4 a4[4], b4[4];
            #pragma unroll
            for (int i = 0; i < 4; i++) a4[i] = *(const float4*)&Ps[(ty + 16 * i) * 68 + kk];
            #pragma unroll
            for (int j = 0; j < 4; j++) b4[j] = *(const float4*)&Vt[(tx + 16 * j) * 68 + kk];
            #pragma unroll
            for (int i = 0; i < 4; i++)
                #pragma unroll
                for (int j = 0; j < 4; j++) {
                    acc[i][j] = fmaf(a4[i].x, b4[j].x, acc[i][j]);
                    acc[i][j] = fmaf(a4[i].y, b4[j].y, acc[i][j]);
                    acc[i][j] = fmaf(a4[i].z, b4[j].z, acc[i][j]);
                    acc[i][j] = fmaf(a4[i].w, b4[j].w, acc[i][j]);
                }
        }
    }

    const int b = bh / H, h = bh % H;
    #pragma unroll
    for (int i = 0; i < 4; i++) {
        const int q  = q0 + ty + 16 * i;
        const float inv = 1.f / lrow[i];
        float* dst = g_att + ((size_t)b * S + q) * D + h * HD + tx;
        #pragma unroll
        for (int j = 0; j < 4; j++)
            dst[16 * j] = acc[i][j] * inv;
    }
}

// ---------------------------------------------------------------------------
extern "C" void kernel_launch(void* const* d_in, const int* in_sizes, int n_in,
                              void* d_out, int out_size)
{
    const float* q  = (const float*)d_in[0];
    const float* k  = (const float*)d_in[1];
    const float* v  = (const float*)d_in[2];
    const float* wq = (const float*)d_in[3];
    const float* wk = (const float*)d_in[4];
    const float* wv = (const float*)d_in[5];
    const float* wo = (const float*)d_in[6];
    float* out = (float*)d_out;

    cudaFuncSetAttribute(attn64, cudaFuncAttributeMaxDynamicSharedMemorySize,
                         ATT_SMEM);
    cudaFuncSetAttribute(gemm_mma, cudaFuncAttributeMaxDynamicSharedMemorySize,
                         GEMM_SMEM);

    const int nX = M * D / 4;
    const int nW = D * D / 4;
    dim3 cb(256);
    dim3 cgX((nX + 255) / 256), cgW((nW + 255) / 256);
    dim3 gg(D / 128, M / 128);    // (8, 32)

    // Q projection
    cvt_split<<<cgW, cb>>>((const float4*)wq, 1, 0, nW);
    cvt_split<<<cgX, cb>>>((const float4*)q,  0, 0, nX);
    gemm_mma<<<gg, cb, GEMM_SMEM>>>(nullptr, 0.125f, 1);
    // K projection
    cvt_split<<<cgW, cb>>>((const float4*)wk, 1, 0, nW);
    cvt_split<<<cgX, cb>>>((const float4*)k,  0, 0, nX);
    gemm_mma<<<gg, cb, GEMM_SMEM>>>(nullptr, 1.0f, 2);
    // V projection
    cvt_split<<<cgW, cb>>>((const float4*)wv, 1, 0, nW);
    cvt_split<<<cgX, cb>>>((const float4*)v,  0, 0, nX);
    gemm_mma<<<gg, cb, GEMM_SMEM>>>(nullptr, 1.0f, 3);
    // attention
    dim3 agrid(S / 64, BH);
    attn64<<<agrid, cb, ATT_SMEM>>>();
    // output projection
    cvt_split<<<cgW, cb>>>((const float4*)wo, 1, 0, nW);
    cvt_split<<<cgX, cb>>>(nullptr, 0, 1, nX);
    gemm_mma<<<gg, cb, GEMM_SMEM>>>(out, 1.0f, 0);
}

// round 11
// speedup vs baseline: 2.9097x; 1.6690x over previous
#include <cuda_runtime.h>
#include <cuda_bf16.h>
#include <math.h>
#include <stdint.h>

// Problem constants
constexpr int B  = 2;
constexpr int S  = 2048;
constexpr int D  = 1024;
constexpr int H  = 16;
constexpr int HD = 64;
constexpr int M  = B * S;       // 4096
constexpr int BH = B * H;       // 32

// ---------------------------------------------------------------------------
// Scratch (__device__ globals) — all bf16 hi/lo split pairs
// ---------------------------------------------------------------------------
__device__ __nv_bfloat16 g_Xh[M * D],      g_Xl[M * D];
__device__ __nv_bfloat16 g_Wh[D * D],      g_Wl[D * D];
__device__ __nv_bfloat16 g_Qh[BH * S * HD], g_Ql[BH * S * HD];   // [bh][s][hd]
__device__ __nv_bfloat16 g_Kh[BH * S * HD], g_Kl[BH * S * HD];   // [bh][s][hd]
__device__ __nv_bfloat16 g_Vth[BH * HD * S], g_Vtl[BH * HD * S]; // [bh][hd][s]

// ---------------------------------------------------------------------------
// mma.sync helpers (sm_80+ PTX)
// ---------------------------------------------------------------------------
__device__ __forceinline__ uint32_t smem_u32(const void* p) {
    uint32_t a;
    asm("{ .reg .u64 t; cvta.to.shared.u64 t, %1; cvt.u32.u64 %0, t; }"
        : "=r"(a) : "l"(p));
    return a;
}

__device__ __forceinline__ void ldmx4(uint32_t* r, uint32_t addr) {
    asm volatile("ldmatrix.sync.aligned.m8n8.x4.shared.b16 {%0,%1,%2,%3}, [%4];"
                 : "=r"(r[0]), "=r"(r[1]), "=r"(r[2]), "=r"(r[3]) : "r"(addr));
}

__device__ __forceinline__ void mma16816(float* d, const uint32_t* a,
                                         const uint32_t* b) {
    asm volatile(
        "mma.sync.aligned.m16n8k16.row.col.f32.bf16.bf16.f32 "
        "{%0,%1,%2,%3}, {%4,%5,%6,%7}, {%8,%9}, {%0,%1,%2,%3};"
        : "+f"(d[0]), "+f"(d[1]), "+f"(d[2]), "+f"(d[3])
        : "r"(a[0]), "r"(a[1]), "r"(a[2]), "r"(a[3]), "r"(b[0]), "r"(b[1]));
}

// fp32 pair -> (bf16x2 hi trunc, bf16x2 lo residual)
__device__ __forceinline__ void split2(float f0, float f1,
                                       uint32_t& hi, uint32_t& lo) {
    uint32_t u0 = __float_as_uint(f0), u1 = __float_as_uint(f1);
    hi = __byte_perm(u0, u1, 0x7632);
    float h0 = __uint_as_float(u0 & 0xFFFF0000u);
    float h1 = __uint_as_float(u1 & 0xFFFF0000u);
    __nv_bfloat162 l = __float22bfloat162_rn(make_float2(f0 - h0, f1 - h1));
    lo = *reinterpret_cast<uint32_t*>(&l);
}
__device__ __forceinline__ void split1(float f, __nv_bfloat16& hi,
                                       __nv_bfloat16& lo) {
    uint32_t u = __float_as_uint(f);
    __nv_bfloat16_raw hr; hr.x = (unsigned short)(u >> 16);
    hi = hr;
    float hf = __uint_as_float(u & 0xFFFF0000u);
    lo = __float2bfloat16_rn(f - hf);
}

// ---------------------------------------------------------------------------
// fp32 -> bf16 hi/lo split pass. dstsel: 0 -> g_X{h,l}, 1 -> g_W{h,l}
// ---------------------------------------------------------------------------
__global__ __launch_bounds__(256)
void cvt_split(const float4* __restrict__ x, int dstsel, int nvec)
{
    int i = blockIdx.x * blockDim.x + threadIdx.x;
    if (i >= nvec) return;
    uint2* hi = dstsel ? (uint2*)g_Wh : (uint2*)g_Xh;
    uint2* lo = dstsel ? (uint2*)g_Wl : (uint2*)g_Xl;

    float4 v = x[i];
    uint2 h, l;
    split2(v.x, v.y, h.x, l.x);
    split2(v.z, v.w, h.y, l.y);
    hi[i] = h;
    lo[i] = l;
}

// ---------------------------------------------------------------------------
// mma.sync GEMM: C = X @ W^T, 128x128 CTA tile, 8 warps 64x32, K-chunks 64.
// Split XhWh + XhWl + XlWh. Epilogue by mode:
//   0 -> fp32 flat Out;  1/2 -> bf16 split g_Q / g_K [bh][s][hd];
//   3 -> bf16 split TRANSPOSED g_Vt [bh][hd][s].
// ---------------------------------------------------------------------------
constexpr int TROWB  = 144;
constexpr int TILE_B = 128 * TROWB;
constexpr int BUF_B  = 4 * TILE_B;
constexpr int GEMM_SMEM = 2 * BUF_B;        // 147456

__global__ __launch_bounds__(256, 1)
void gemm_mma(float* __restrict__ Out, float scale, int mode)
{
    extern __shared__ __align__(128) char smem[];
    const uint32_t sb = smem_u32(smem);
    const int tid  = threadIdx.x;
    const int lane = tid & 31;
    const int wid  = tid >> 5;
    const int wm   = wid >> 2;
    const int wn   = wid & 3;
    const int col0 = blockIdx.x * 128;
    const int row0 = blockIdx.y * 128;

    const __nv_bfloat16* srcs[4] = {
        g_Xh + (size_t)row0 * D, g_Xl + (size_t)row0 * D,
        g_Wh + (size_t)col0 * D, g_Wl + (size_t)col0 * D };

    auto load_chunk = [&](int kt, int buf) {
        char* bs = smem + buf * BUF_B;
        const int kbytes = kt * 128;
        #pragma unroll
        for (int t = 0; t < 4; t++) {
            const char* g = (const char*)srcs[t] + kbytes;
            char* sd = bs + t * TILE_B;
            #pragma unroll
            for (int p = 0; p < 4; p++) {
                int u = tid + p * 256;
                int r = u >> 3, c16 = (u & 7) * 16;
                uint4 v = *(const uint4*)(g + (size_t)r * 2048 + c16);
                *(uint4*)(sd + r * TROWB + c16) = v;
            }
        }
    };

    float c[4][4][4] = {};

    load_chunk(0, 0);
    __syncthreads();

    for (int kt = 0; kt < 16; kt++) {
        const int buf = kt & 1;
        if (kt < 15) load_chunk(kt + 1, buf ^ 1);

        const uint32_t base = sb + buf * BUF_B;
        #pragma unroll
        for (int ks = 0; ks < 4; ks++) {
            const int k0 = ks * 16;
            uint32_t ah[4][4], al[4][4];
            {
                const uint32_t rofs = (uint32_t)(wm * 64 + (lane & 15)) * TROWB
                                    + (uint32_t)(k0 + (lane >> 4) * 8) * 2;
                #pragma unroll
                for (int i = 0; i < 4; i++) {
                    ldmx4(ah[i], base + 0 * TILE_B + rofs + i * 16 * TROWB);
                    ldmx4(al[i], base + 1 * TILE_B + rofs + i * 16 * TROWB);
                }
            }
            uint32_t bh[4][2], bl[4][2];
            {
                const uint32_t rpart = (uint32_t)(wn * 32 + (lane >> 4) * 8
                                                  + (lane & 7)) * TROWB
                                     + (uint32_t)(k0 + ((lane >> 3) & 1) * 8) * 2;
                #pragma unroll
                for (int pr = 0; pr < 2; pr++) {
                    uint32_t r4[4];
                    ldmx4(r4, base + 2 * TILE_B + rpart + pr * 16 * TROWB);
                    bh[pr * 2 + 0][0] = r4[0]; bh[pr * 2 + 0][1] = r4[1];
                    bh[pr * 2 + 1][0] = r4[2]; bh[pr * 2 + 1][1] = r4[3];
                    ldmx4(r4, base + 3 * TILE_B + rpart + pr * 16 * TROWB);
                    bl[pr * 2 + 0][0] = r4[0]; bl[pr * 2 + 0][1] = r4[1];
                    bl[pr * 2 + 1][0] = r4[2]; bl[pr * 2 + 1][1] = r4[3];
                }
            }
            #pragma unroll
            for (int i = 0; i < 4; i++)
                #pragma unroll
                for (int j = 0; j < 4; j++) {
                    mma16816(c[i][j], ah[i], bh[j]);
                    mma16816(c[i][j], ah[i], bl[j]);
                    mma16816(c[i][j], al[i], bh[j]);
                }
        }
        __syncthreads();
    }

    const int g = lane >> 2, t2 = (lane & 3) * 2;
    #pragma unroll
    for (int i = 0; i < 4; i++) {
        #pragma unroll
        for (int half = 0; half < 2; half++) {
            const int gr = row0 + wm * 64 + i * 16 + g + half * 8;
            #pragma unroll
            for (int j = 0; j < 4; j++) {
                const int gc = col0 + wn * 32 + j * 8 + t2;
                float f0 = c[i][j][half * 2 + 0] * scale;
                float f1 = c[i][j][half * 2 + 1] * scale;
                if (mode == 0) {
                    *(float2*)&Out[(size_t)gr * D + gc] = make_float2(f0, f1);
                } else {
                    const int b = gr >> 11, s_ = gr & (S - 1);
                    const int h = gc >> 6, hd = gc & 63;
                    if (mode == 3) {   // transposed V
                        const size_t rb = (size_t)(b * H + h) * HD;
                        __nv_bfloat16 hi, lo;
                        split1(f0, hi, lo);
                        g_Vth[(rb + hd) * S + s_] = hi;
                        g_Vtl[(rb + hd) * S + s_] = lo;
                        split1(f1, hi, lo);
                        g_Vth[(rb + hd + 1) * S + s_] = hi;
                        g_Vtl[(rb + hd + 1) * S + s_] = lo;
                    } else {
                        __nv_bfloat16* dh = (mode == 1) ? g_Qh : g_Kh;
                        __nv_bfloat16* dl = (mode == 1) ? g_Ql : g_Kl;
                        const size_t idx = (((size_t)(b * H + h) * S) + s_) * HD + hd;
                        uint32_t hi, lo;
                        split2(f0, f1, hi, lo);
                        ((uint32_t*)dh)[idx >> 1] = hi;
                        ((uint32_t*)dl)[idx >> 1] = lo;
                    }
                }
            }
        }
    }
}

// ---------------------------------------------------------------------------
// Tensor-core flash attention, causal, bf16 3-way split throughout.
// CTA = 128 q-rows x (b,h); 8 warps each own m16 x n128 of the score tile.
// K tiles [128 s][64 hd] hi/lo; V tiles transposed [64 hd][128 s] hi/lo.
// ---------------------------------------------------------------------------
constexpr int VROWB   = 272;                       // 128 halves + 8 pad
constexpr int QH_OFF  = 0;
constexpr int QL_OFF  = 18432;                     // 128*144
constexpr int KBUF_OFF = 36864;                    // 2 bufs, stride 36864 (Kh,Kl)
constexpr int VBUF_OFF = 110592;                   // 2 bufs, stride 34816 (Vh,Vl)
constexpr int ATT_SMEM = 180224;

__global__ __launch_bounds__(256, 1)
void attn_mma()
{
    extern __shared__ __align__(128) char smem[];
    const uint32_t sb = smem_u32(smem);
    const int tid  = threadIdx.x;
    const int lane = tid & 31;
    const int wid  = tid >> 5;
    const int qt   = 15 - (int)blockIdx.x;     // heavy q-tiles first
    const int bhi  = blockIdx.y;
    const int q0   = qt * 128;

    const char* Qhp = (const char*)(g_Qh + (size_t)bhi * S * HD) + (size_t)q0 * 128;
    const char* Qlp = (const char*)(g_Ql + (size_t)bhi * S * HD) + (size_t)q0 * 128;
    const char* Khp = (const char*)(g_Kh + (size_t)bhi * S * HD);
    const char* Klp = (const char*)(g_Kl + (size_t)bhi * S * HD);
    const char* Vhp = (const char*)(g_Vth + (size_t)bhi * HD * S);
    const char* Vlp = (const char*)(g_Vtl + (size_t)bhi * HD * S);

    // Q tiles (once): 128 rows x 128B, hi+lo
    #pragma unroll
    for (int p = 0; p < 4; p++) {
        int u = tid + p * 256;
        int r = u >> 3, c16 = (u & 7) * 16;
        *(uint4*)(smem + QH_OFF + r * TROWB + c16) =
            *(const uint4*)(Qhp + (size_t)r * 128 + c16);
        *(uint4*)(smem + QL_OFF + r * TROWB + c16) =
            *(const uint4*)(Qlp + (size_t)r * 128 + c16);
    }

    auto loadKV = [&](int kt, int buf) {
        char* kb = smem + KBUF_OFF + buf * 36864;
        char* vb = smem + VBUF_OFF + buf * 34816;
        const size_t kbyte = (size_t)kt * 128 * 128;   // K row offset (bytes)
        const size_t vbyte = (size_t)kt * 128 * 2;     // V col offset (bytes)
        #pragma unroll
        for (int p = 0; p < 4; p++) {
            int u = tid + p * 256;
            int r = u >> 3, c16 = (u & 7) * 16;
            *(uint4*)(kb + r * TROWB + c16) =
                *(const uint4*)(Khp + kbyte + (size_t)r * 128 + c16);
            *(uint4*)(kb + 18432 + r * TROWB + c16) =
                *(const uint4*)(Klp + kbyte + (size_t)r * 128 + c16);
            int rv = u >> 4, cv = (u & 15) * 16;
            *(uint4*)(vb + rv * VROWB + cv) =
                *(const uint4*)(Vhp + (size_t)rv * (S * 2) + vbyte + cv);
            *(uint4*)(vb + 17408 + rv * VROWB + cv) =
                *(const uint4*)(Vlp + (size_t)rv * (S * 2) + vbyte + cv);
        }
    };

    loadKV(0, 0);
    __syncthreads();

    float o[8][4] = {};
    float mrow[2] = {-1e30f, -1e30f}, lrow[2] = {0.f, 0.f};

    const uint32_t a_rofs = (uint32_t)(wid * 16 + (lane & 15)) * TROWB
                          + (uint32_t)((lane >> 4) * 8) * 2;
    const uint32_t b_rofs = (uint32_t)((lane >> 4) * 8 + (lane & 7)) * TROWB
                          + (uint32_t)(((lane >> 3) & 1) * 8) * 2;
    const uint32_t v_rofs = (uint32_t)((lane >> 4) * 8 + (lane & 7)) * VROWB
                          + (uint32_t)(((lane >> 3) & 1) * 8) * 2;

    for (int kt = 0; kt <= qt; kt++) {
        const int buf = kt & 1;
        if (kt < qt) loadKV(kt + 1, buf ^ 1);

        // ----- S = Q.K^T (fp32 accum, 3-way split) -----
        float sf[16][4] = {};
        const uint32_t kb = sb + KBUF_OFF + buf * 36864;
        #pragma unroll
        for (int ks = 0; ks < 4; ks++) {
            uint32_t ah[4], al[4];
            ldmx4(ah, sb + QH_OFF + a_rofs + ks * 32);
            ldmx4(al, sb + QL_OFF + a_rofs + ks * 32);
            #pragma unroll
            for (int jj = 0; jj < 8; jj++) {
                uint32_t r4[4], l4[4];
                ldmx4(r4, kb + jj * 16 * TROWB + b_rofs + ks * 32);
                ldmx4(l4, kb + 18432 + jj * 16 * TROWB + b_rofs + ks * 32);
                uint32_t b0h[2] = {r4[0], r4[1]}, b1h[2] = {r4[2], r4[3]};
                uint32_t b0l[2] = {l4[0], l4[1]}, b1l[2] = {l4[2], l4[3]};
                mma16816(sf[2 * jj],     ah, b0h);
                mma16816(sf[2 * jj],     ah, b0l);
                mma16816(sf[2 * jj],     al, b0h);
                mma16816(sf[2 * jj + 1], ah, b1h);
                mma16816(sf[2 * jj + 1], ah, b1l);
                mma16816(sf[2 * jj + 1], al, b1h);
            }
        }

        // ----- causal mask on diagonal tile -----
        if (kt == qt) {
            const int rb = wid * 16 + (lane >> 2);
            const int cb = (lane & 3) * 2;
            #pragma unroll
            for (int j = 0; j < 16; j++)
                #pragma unroll
                for (int e = 0; e < 4; e++) {
                    int row = rb + (e >> 1) * 8;
                    int col = j * 8 + cb + (e & 1);
                    if (col > row) sf[j][e] = -1e30f;
                }
        }

        // ----- online softmax (rows live in 4-lane quads) -----
        #pragma unroll
        for (int h2 = 0; h2 < 2; h2++) {
            float mx = -1e30f;
            #pragma unroll
            for (int j = 0; j < 16; j++)
                mx = fmaxf(mx, fmaxf(sf[j][h2 * 2], sf[j][h2 * 2 + 1]));
            mx = fmaxf(mx, __shfl_xor_sync(0xffffffffu, mx, 1));
            mx = fmaxf(mx, __shfl_xor_sync(0xffffffffu, mx, 2));
            const float mn   = fmaxf(mrow[h2], mx);
            const float corr = __expf(mrow[h2] - mn);
            float rs = 0.f;
            #pragma unroll
            for (int j = 0; j < 16; j++) {
                sf[j][h2 * 2]     = __expf(sf[j][h2 * 2]     - mn);
                sf[j][h2 * 2 + 1] = __expf(sf[j][h2 * 2 + 1] - mn);
                rs += sf[j][h2 * 2] + sf[j][h2 * 2 + 1];
            }
            rs += __shfl_xor_sync(0xffffffffu, rs, 1);
            rs += __shfl_xor_sync(0xffffffffu, rs, 2);
            lrow[h2] = lrow[h2] * corr + rs;
            mrow[h2] = mn;
            #pragma unroll
            for (int j = 0; j < 8; j++) {
                o[j][h2 * 2]     *= corr;
                o[j][h2 * 2 + 1] *= corr;
            }
        }

        // ----- O += P.V (P from S accumulators, split; V transposed) -----
        const uint32_t vb = sb + VBUF_OFF + buf * 34816;
        #pragma unroll
        for (int ks2 = 0; ks2 < 8; ks2++) {
            uint32_t pah[4], pal[4];
            #pragma unroll
            for (int t = 0; t < 2; t++)
                #pragma unroll
                for (int h2 = 0; h2 < 2; h2++)
                    split2(sf[2 * ks2 + t][h2 * 2], sf[2 * ks2 + t][h2 * 2 + 1],
                           pah[t * 2 + h2], pal[t * 2 + h2]);
            #pragma unroll
            for (int jj = 0; jj < 4; jj++) {
                uint32_t r4[4], l4[4];
                ldmx4(r4, vb + jj * 16 * VROWB + v_rofs + ks2 * 32);
                ldmx4(l4, vb + 17408 + jj * 16 * VROWB + v_rofs + ks2 * 32);
                uint32_t b0h[2] = {r4[0], r4[1]}, b1h[2] = {r4[2], r4[3]};
                uint32_t b0l[2] = {l4[0], l4[1]}, b1l[2] = {l4[2], l4[3]};
                mma16816(o[2 * jj],     pah, b0h);
                mma16816(o[2 * jj],     pah, b0l);
                mma16816(o[2 * jj],     pal, b0h);
                mma16816(o[2 * jj + 1], pah, b1h);
                mma16816(o[2 * jj + 1], pah, b1l);
                mma16816(o[2 * jj + 1], pal, b1h);
            }
        }
        __syncthreads();
    }

    // ----- epilogue: normalize + split-write into g_Xh/g_Xl [b*S+s][D] -----
    const int b = bhi >> 4, h = bhi & 15;
    const int r = lane >> 2, c2 = (lane & 3) * 2;
    #pragma unroll
    for (int h2 = 0; h2 < 2; h2++) {
        const int row = b * S + q0 + wid * 16 + r + h2 * 8;
        const float inv = 1.f / lrow[h2];
        #pragma unroll
        for (int j = 0; j < 8; j++) {
            const int col = h * 64 + j * 8 + c2;
            uint32_t hi, lo;
            split2(o[j][h2 * 2] * inv, o[j][h2 * 2 + 1] * inv, hi, lo);
            const size_t idx = (size_t)row * D + col;
            ((uint32_t*)g_Xh)[idx >> 1] = hi;
            ((uint32_t*)g_Xl)[idx >> 1] = lo;
        }
    }
}

// ---------------------------------------------------------------------------
extern "C" void kernel_launch(void* const* d_in, const int* in_sizes, int n_in,
                              void* d_out, int out_size)
{
    const float* q  = (const float*)d_in[0];
    const float* k  = (const float*)d_in[1];
    const float* v  = (const float*)d_in[2];
    const float* wq = (const float*)d_in[3];
    const float* wk = (const float*)d_in[4];
    const float* wv = (const float*)d_in[5];
    const float* wo = (const float*)d_in[6];
    float* out = (float*)d_out;

    cudaFuncSetAttribute(gemm_mma, cudaFuncAttributeMaxDynamicSharedMemorySize,
                         GEMM_SMEM);
    cudaFuncSetAttribute(attn_mma, cudaFuncAttributeMaxDynamicSharedMemorySize,
                         ATT_SMEM);

    const int nX = M * D / 4;
    const int nW = D * D / 4;
    dim3 cb(256);
    dim3 cgX((nX + 255) / 256), cgW((nW + 255) / 256);
    dim3 gg(D / 128, M / 128);     // (8, 32)

    // Q projection -> g_Qh/l (scale folds 1/sqrt(64))
    cvt_split<<<cgW, cb>>>((const float4*)wq, 1, nW);
    cvt_split<<<cgX, cb>>>((const float4*)q,  0, nX);
    gemm_mma<<<gg, cb, GEMM_SMEM>>>(nullptr, 0.125f, 1);
    // K projection -> g_Kh/l
    cvt_split<<<cgW, cb>>>((const float4*)wk, 1, nW);
    cvt_split<<<cgX, cb>>>((const float4*)k,  0, nX);
    gemm_mma<<<gg, cb, GEMM_SMEM>>>(nullptr, 1.0f, 2);
    // V projection -> g_Vth/l (transposed)
    cvt_split<<<cgW, cb>>>((const float4*)wv, 1, nW);
    cvt_split<<<cgX, cb>>>((const float4*)v,  0, nX);
    gemm_mma<<<gg, cb, GEMM_SMEM>>>(nullptr, 1.0f, 3);
    // attention -> writes g_Xh/g_Xl directly
    dim3 agrid(16, BH);
    attn_mma<<<agrid, cb, ATT_SMEM>>>();
    // output projection
    cvt_split<<<cgW, cb>>>((const float4*)wo, 1, nW);
    gemm_mma<<<gg, cb, GEMM_SMEM>>>(out, 1.0f, 0);
}

// round 12
// speedup vs baseline: 3.1430x; 1.0802x over previous
#include <cuda_runtime.h>
#include <cuda_bf16.h>
#include <math.h>
#include <stdint.h>

// Problem constants
constexpr int B  = 2;
constexpr int S  = 2048;
constexpr int D  = 1024;
constexpr int H  = 16;
constexpr int HD = 64;
constexpr int M  = B * S;       // 4096
constexpr int BH = B * H;       // 32

// ---------------------------------------------------------------------------
// Scratch (__device__ globals) — bf16 hi/lo split pairs.
// X: 3 slots (q,k,v inputs; slot 0 reused for attention output).
// W: 4 slots (wq,wk,wv,wo).
// ---------------------------------------------------------------------------
__device__ __nv_bfloat16 g_Xh[3 * M * D],  g_Xl[3 * M * D];
__device__ __nv_bfloat16 g_Wh[4 * D * D],  g_Wl[4 * D * D];
__device__ __nv_bfloat16 g_Qh[BH * S * HD], g_Ql[BH * S * HD];   // [bh][s][hd]
__device__ __nv_bfloat16 g_Kh[BH * S * HD], g_Kl[BH * S * HD];   // [bh][s][hd]
__device__ __nv_bfloat16 g_Vth[BH * HD * S], g_Vtl[BH * HD * S]; // [bh][hd][s]

// ---------------------------------------------------------------------------
// PTX helpers (sm_80+ — valid on target sm_100)
// ---------------------------------------------------------------------------
__device__ __forceinline__ uint32_t smem_u32(const void* p) {
    uint32_t a;
    asm("{ .reg .u64 t; cvta.to.shared.u64 t, %1; cvt.u32.u64 %0, t; }"
        : "=r"(a) : "l"(p));
    return a;
}

__device__ __forceinline__ void ldmx4(uint32_t* r, uint32_t addr) {
    asm volatile("ldmatrix.sync.aligned.m8n8.x4.shared.b16 {%0,%1,%2,%3}, [%4];"
                 : "=r"(r[0]), "=r"(r[1]), "=r"(r[2]), "=r"(r[3]) : "r"(addr));
}

__device__ __forceinline__ void mma16816(float* d, const uint32_t* a,
                                         const uint32_t* b) {
    asm volatile(
        "mma.sync.aligned.m16n8k16.row.col.f32.bf16.bf16.f32 "
        "{%0,%1,%2,%3}, {%4,%5,%6,%7}, {%8,%9}, {%0,%1,%2,%3};"
        : "+f"(d[0]), "+f"(d[1]), "+f"(d[2]), "+f"(d[3])
        : "r"(a[0]), "r"(a[1]), "r"(a[2]), "r"(a[3]), "r"(b[0]), "r"(b[1]));
}

__device__ __forceinline__ void cp16(uint32_t saddr, const void* g) {
    asm volatile("cp.async.cg.shared.global [%0], [%1], 16;"
                 :: "r"(saddr), "l"(g));
}
#define CP_COMMIT() asm volatile("cp.async.commit_group;" ::: "memory")
#define CP_WAIT0()  asm volatile("cp.async.wait_group 0;" ::: "memory")

// fp32 pair -> (bf16x2 hi trunc, bf16x2 lo residual)
__device__ __forceinline__ void split2(float f0, float f1,
                                       uint32_t& hi, uint32_t& lo) {
    uint32_t u0 = __float_as_uint(f0), u1 = __float_as_uint(f1);
    hi = __byte_perm(u0, u1, 0x7632);
    float h0 = __uint_as_float(u0 & 0xFFFF0000u);
    float h1 = __uint_as_float(u1 & 0xFFFF0000u);
    __nv_bfloat162 l = __float22bfloat162_rn(make_float2(f0 - h0, f1 - h1));
    lo = *reinterpret_cast<uint32_t*>(&l);
}
__device__ __forceinline__ void split1(float f, __nv_bfloat16& hi,
                                       __nv_bfloat16& lo) {
    uint32_t u = __float_as_uint(f);
    __nv_bfloat16_raw hr; hr.x = (unsigned short)(u >> 16);
    hi = hr;
    float hf = __uint_as_float(u & 0xFFFF0000u);
    lo = __float2bfloat16_rn(f - hf);
}

// ---------------------------------------------------------------------------
// Fused fp32 -> bf16 hi/lo split for all 7 inputs in ONE launch.
// blockIdx.y: 0..2 -> X slots 0..2 (q,k,v), 3..6 -> W slots 0..3 (wq,wk,wv,wo)
// ---------------------------------------------------------------------------
__global__ __launch_bounds__(256)
void cvt_all(const float4* __restrict__ q,  const float4* __restrict__ k,
             const float4* __restrict__ v,  const float4* __restrict__ wq,
             const float4* __restrict__ wk, const float4* __restrict__ wv,
             const float4* __restrict__ wo)
{
    const int which = blockIdx.y;
    const int i = blockIdx.x * blockDim.x + threadIdx.x;
    const float4* src;
    uint2 *hi, *lo;
    int nvec;
    if (which < 3) {
        src = (which == 0) ? q : (which == 1) ? k : v;
        hi = (uint2*)g_Xh + (size_t)which * (M * D / 4);
        lo = (uint2*)g_Xl + (size_t)which * (M * D / 4);
        nvec = M * D / 4;
    } else {
        const int ws = which - 3;
        src = (ws == 0) ? wq : (ws == 1) ? wk : (ws == 2) ? wv : wo;
        hi = (uint2*)g_Wh + (size_t)ws * (D * D / 4);
        lo = (uint2*)g_Wl + (size_t)ws * (D * D / 4);
        nvec = D * D / 4;
    }
    if (i >= nvec) return;
    float4 x = src[i];
    uint2 h, l;
    split2(x.x, x.y, h.x, l.x);
    split2(x.z, x.w, h.y, l.y);
    hi[i] = h;
    lo[i] = l;
}

// ---------------------------------------------------------------------------
// mma.sync GEMM: C = X @ W^T, 128x128 CTA tile, 8 warps 64x32.
// K-chunk 32 + cp.async double-buffer -> 80KB smem -> 2 CTAs/SM.
// Split XhWh + XhWl + XlWh.
// omode 1: fused QKV (blockIdx.z picks X/W slot + destination).
// omode 0: O-projection (X slot 0, W slot 3, fp32 flat Out).
// ---------------------------------------------------------------------------
constexpr int GROWB = 80;                  // 32 data halves + 8 pad
constexpr int GTILE = 128 * GROWB;         // 10240 B
constexpr int GBUF  = 4 * GTILE;           // Xh,Xl,Wh,Wl = 40960 B
constexpr int GEMM_SMEM = 2 * GBUF;        // 81920 B -> 2 CTAs/SM

__global__ __launch_bounds__(256, 2)
void gemm_mma(float* __restrict__ Out, int omode)
{
    extern __shared__ __align__(128) char smem[];
    const uint32_t sb = smem_u32(smem);
    const int tid  = threadIdx.x;
    const int lane = tid & 31;
    const int wid  = tid >> 5;
    const int wm   = wid >> 2;
    const int wn   = wid & 3;
    const int col0 = blockIdx.x * 128;
    const int row0 = blockIdx.y * 128;
    const int z    = blockIdx.z;

    int xs, ws, mode;
    float scale;
    if (omode == 0) { xs = 0; ws = 3; scale = 1.0f;  mode = 0; }
    else            { xs = z; ws = z; scale = (z == 0) ? 0.125f : 1.0f; mode = 1 + z; }

    const __nv_bfloat16* srcs[4] = {
        g_Xh + (size_t)xs * M * D + (size_t)row0 * D,
        g_Xl + (size_t)xs * M * D + (size_t)row0 * D,
        g_Wh + (size_t)ws * D * D + (size_t)col0 * D,
        g_Wl + (size_t)ws * D * D + (size_t)col0 * D };

    // chunk loader: 4 tiles x 128 rows x 64B, cp.async, 8 ops/thread
    auto load_chunk = [&](int kt, int buf) {
        const uint32_t bs = sb + buf * GBUF;
        const int kbytes = kt * 64;        // 32 halves per chunk
        #pragma unroll
        for (int t = 0; t < 4; t++) {
            const char* g = (const char*)srcs[t] + kbytes;
            const uint32_t sd = bs + t * GTILE;
            #pragma unroll
            for (int p = 0; p < 2; p++) {
                int u = tid + p * 256;
                int r = u >> 2, c16 = (u & 3) * 16;
                cp16(sd + r * GROWB + c16, g + (size_t)r * 2048 + c16);
            }
        }
    };

    float c[4][4][4] = {};

    load_chunk(0, 0);
    CP_COMMIT();
    CP_WAIT0();
    __syncthreads();

    for (int kt = 0; kt < 32; kt++) {
        const int buf = kt & 1;
        if (kt < 31) { load_chunk(kt + 1, buf ^ 1); CP_COMMIT(); }

        const uint32_t base = sb + buf * GBUF;
        #pragma unroll
        for (int ks = 0; ks < 2; ks++) {
            const int k0 = ks * 16;
            uint32_t ah[4][4], al[4][4];
            {
                const uint32_t rofs = (uint32_t)(wm * 64 + (lane & 15)) * GROWB
                                    + (uint32_t)(k0 + (lane >> 4) * 8) * 2;
                #pragma unroll
                for (int i = 0; i < 4; i++) {
                    ldmx4(ah[i], base + 0 * GTILE + rofs + i * 16 * GROWB);
                    ldmx4(al[i], base + 1 * GTILE + rofs + i * 16 * GROWB);
                }
            }
            uint32_t bh[4][2], bl[4][2];
            {
                const uint32_t rpart = (uint32_t)(wn * 32 + (lane >> 4) * 8
                                                  + (lane & 7)) * GROWB
                                     + (uint32_t)(k0 + ((lane >> 3) & 1) * 8) * 2;
                #pragma unroll
                for (int pr = 0; pr < 2; pr++) {
                    uint32_t r4[4];
                    ldmx4(r4, base + 2 * GTILE + rpart + pr * 16 * GROWB);
                    bh[pr * 2 + 0][0] = r4[0]; bh[pr * 2 + 0][1] = r4[1];
                    bh[pr * 2 + 1][0] = r4[2]; bh[pr * 2 + 1][1] = r4[3];
                    ldmx4(r4, base + 3 * GTILE + rpart + pr * 16 * GROWB);
                    bl[pr * 2 + 0][0] = r4[0]; bl[pr * 2 + 0][1] = r4[1];
                    bl[pr * 2 + 1][0] = r4[2]; bl[pr * 2 + 1][1] = r4[3];
                }
            }
            #pragma unroll
            for (int i = 0; i < 4; i++)
                #pragma unroll
                for (int j = 0; j < 4; j++) {
                    mma16816(c[i][j], ah[i], bh[j]);
                    mma16816(c[i][j], ah[i], bl[j]);
                    mma16816(c[i][j], al[i], bh[j]);
                }
        }
        if (kt < 31) CP_WAIT0();
        __syncthreads();
    }

    // Epilogue
    const int g = lane >> 2, t2 = (lane & 3) * 2;
    #pragma unroll
    for (int i = 0; i < 4; i++) {
        #pragma unroll
        for (int half = 0; half < 2; half++) {
            const int gr = row0 + wm * 64 + i * 16 + g + half * 8;
            #pragma unroll
            for (int j = 0; j < 4; j++) {
                const int gc = col0 + wn * 32 + j * 8 + t2;
                float f0 = c[i][j][half * 2 + 0] * scale;
                float f1 = c[i][j][half * 2 + 1] * scale;
                if (mode == 0) {
                    *(float2*)&Out[(size_t)gr * D + gc] = make_float2(f0, f1);
                } else {
                    const int b = gr >> 11, s_ = gr & (S - 1);
                    const int h = gc >> 6, hd = gc & 63;
                    if (mode == 3) {   // transposed V
                        const size_t rb = (size_t)(b * H + h) * HD;
                        __nv_bfloat16 hi, lo;
                        split1(f0, hi, lo);
                        g_Vth[(rb + hd) * S + s_] = hi;
                        g_Vtl[(rb + hd) * S + s_] = lo;
                        split1(f1, hi, lo);
                        g_Vth[(rb + hd + 1) * S + s_] = hi;
                        g_Vtl[(rb + hd + 1) * S + s_] = lo;
                    } else {
                        __nv_bfloat16* dh = (mode == 1) ? g_Qh : g_Kh;
                        __nv_bfloat16* dl = (mode == 1) ? g_Ql : g_Kl;
                        const size_t idx = (((size_t)(b * H + h) * S) + s_) * HD + hd;
                        uint32_t hi, lo;
                        split2(f0, f1, hi, lo);
                        ((uint32_t*)dh)[idx >> 1] = hi;
                        ((uint32_t*)dl)[idx >> 1] = lo;
                    }
                }
            }
        }
    }
}

// ---------------------------------------------------------------------------
// Tensor-core flash attention (UNCHANGED from R11 passing version).
// CTA = 128 q-rows x (b,h); 8 warps each own m16 x n128 of the score tile.
// ---------------------------------------------------------------------------
constexpr int TROWB   = 144;
constexpr int VROWB   = 272;                       // 128 halves + 8 pad
constexpr int QH_OFF  = 0;
constexpr int QL_OFF  = 18432;                     // 128*144
constexpr int KBUF_OFF = 36864;                    // 2 bufs, stride 36864 (Kh,Kl)
constexpr int VBUF_OFF = 110592;                   // 2 bufs, stride 34816 (Vh,Vl)
constexpr int ATT_SMEM = 180224;

__global__ __launch_bounds__(256, 1)
void attn_mma()
{
    extern __shared__ __align__(128) char smem[];
    const uint32_t sb = smem_u32(smem);
    const int tid  = threadIdx.x;
    const int lane = tid & 31;
    const int wid  = tid >> 5;
    const int qt   = 15 - (int)blockIdx.x;     // heavy q-tiles first
    const int bhi  = blockIdx.y;
    const int q0   = qt * 128;

    const char* Qhp = (const char*)(g_Qh + (size_t)bhi * S * HD) + (size_t)q0 * 128;
    const char* Qlp = (const char*)(g_Ql + (size_t)bhi * S * HD) + (size_t)q0 * 128;
    const char* Khp = (const char*)(g_Kh + (size_t)bhi * S * HD);
    const char* Klp = (const char*)(g_Kl + (size_t)bhi * S * HD);
    const char* Vhp = (const char*)(g_Vth + (size_t)bhi * HD * S);
    const char* Vlp = (const char*)(g_Vtl + (size_t)bhi * HD * S);

    // Q tiles (once): 128 rows x 128B, hi+lo
    #pragma unroll
    for (int p = 0; p < 4; p++) {
        int u = tid + p * 256;
        int r = u >> 3, c16 = (u & 7) * 16;
        *(uint4*)(smem + QH_OFF + r * TROWB + c16) =
            *(const uint4*)(Qhp + (size_t)r * 128 + c16);
        *(uint4*)(smem + QL_OFF + r * TROWB + c16) =
            *(const uint4*)(Qlp + (size_t)r * 128 + c16);
    }

    auto loadKV = [&](int kt, int buf) {
        char* kb = smem + KBUF_OFF + buf * 36864;
        char* vb = smem + VBUF_OFF + buf * 34816;
        const size_t kbyte = (size_t)kt * 128 * 128;   // K row offset (bytes)
        const size_t vbyte = (size_t)kt * 128 * 2;     // V col offset (bytes)
        #pragma unroll
        for (int p = 0; p < 4; p++) {
            int u = tid + p * 256;
            int r = u >> 3, c16 = (u & 7) * 16;
            *(uint4*)(kb + r * TROWB + c16) =
                *(const uint4*)(Khp + kbyte + (size_t)r * 128 + c16);
            *(uint4*)(kb + 18432 + r * TROWB + c16) =
                *(const uint4*)(Klp + kbyte + (size_t)r * 128 + c16);
            int rv = u >> 4, cv = (u & 15) * 16;
            *(uint4*)(vb + rv * VROWB + cv) =
                *(const uint4*)(Vhp + (size_t)rv * (S * 2) + vbyte + cv);
            *(uint4*)(vb + 17408 + rv * VROWB + cv) =
                *(const uint4*)(Vlp + (size_t)rv * (S * 2) + vbyte + cv);
        }
    };

    loadKV(0, 0);
    __syncthreads();

    float o[8][4] = {};
    float mrow[2] = {-1e30f, -1e30f}, lrow[2] = {0.f, 0.f};

    const uint32_t a_rofs = (uint32_t)(wid * 16 + (lane & 15)) * TROWB
                          + (uint32_t)((lane >> 4) * 8) * 2;
    const uint32_t b_rofs = (uint32_t)((lane >> 4) * 8 + (lane & 7)) * TROWB
                          + (uint32_t)(((lane >> 3) & 1) * 8) * 2;
    const uint32_t v_rofs = (uint32_t)((lane >> 4) * 8 + (lane & 7)) * VROWB
                          + (uint32_t)(((lane >> 3) & 1) * 8) * 2;

    for (int kt = 0; kt <= qt; kt++) {
        const int buf = kt & 1;
        if (kt < qt) loadKV(kt + 1, buf ^ 1);

        // ----- S = Q.K^T (fp32 accum, 3-way split) -----
        float sf[16][4] = {};
        const uint32_t kb = sb + KBUF_OFF + buf * 36864;
        #pragma unroll
        for (int ks = 0; ks < 4; ks++) {
            uint32_t ah[4], al[4];
            ldmx4(ah, sb + QH_OFF + a_rofs + ks * 32);
            ldmx4(al, sb + QL_OFF + a_rofs + ks * 32);
            #pragma unroll
            for (int jj = 0; jj < 8; jj++) {
                uint32_t r4[4], l4[4];
                ldmx4(r4, kb + jj * 16 * TROWB + b_rofs + ks * 32);
                ldmx4(l4, kb + 18432 + jj * 16 * TROWB + b_rofs + ks * 32);
                uint32_t b0h[2] = {r4[0], r4[1]}, b1h[2] = {r4[2], r4[3]};
                uint32_t b0l[2] = {l4[0], l4[1]}, b1l[2] = {l4[2], l4[3]};
                mma16816(sf[2 * jj],     ah, b0h);
                mma16816(sf[2 * jj],     ah, b0l);
                mma16816(sf[2 * jj],     al, b0h);
                mma16816(sf[2 * jj + 1], ah, b1h);
                mma16816(sf[2 * jj + 1], ah, b1l);
                mma16816(sf[2 * jj + 1], al, b1h);
            }
        }

        // ----- causal mask on diagonal tile -----
        if (kt == qt) {
            const int rb = wid * 16 + (lane >> 2);
            const int cb = (lane & 3) * 2;
            #pragma unroll
            for (int j = 0; j < 16; j++)
                #pragma unroll
                for (int e = 0; e < 4; e++) {
                    int row = rb + (e >> 1) * 8;
                    int col = j * 8 + cb + (e & 1);
                    if (col > row) sf[j][e] = -1e30f;
                }
        }

        // ----- online softmax (rows live in 4-lane quads) -----
        #pragma unroll
        for (int h2 = 0; h2 < 2; h2++) {
            float mx = -1e30f;
            #pragma unroll
            for (int j = 0; j < 16; j++)
                mx = fmaxf(mx, fmaxf(sf[j][h2 * 2], sf[j][h2 * 2 + 1]));
            mx = fmaxf(mx, __shfl_xor_sync(0xffffffffu, mx, 1));
            mx = fmaxf(mx, __shfl_xor_sync(0xffffffffu, mx, 2));
            const float mn   = fmaxf(mrow[h2], mx);
            const float corr = __expf(mrow[h2] - mn);
            float rs = 0.f;
            #pragma unroll
            for (int j = 0; j < 16; j++) {
                sf[j][h2 * 2]     = __expf(sf[j][h2 * 2]     - mn);
                sf[j][h2 * 2 + 1] = __expf(sf[j][h2 * 2 + 1] - mn);
                rs += sf[j][h2 * 2] + sf[j][h2 * 2 + 1];
            }
            rs += __shfl_xor_sync(0xffffffffu, rs, 1);
            rs += __shfl_xor_sync(0xffffffffu, rs, 2);
            lrow[h2] = lrow[h2] * corr + rs;
            mrow[h2] = mn;
            #pragma unroll
            for (int j = 0; j < 8; j++) {
                o[j][h2 * 2]     *= corr;
                o[j][h2 * 2 + 1] *= corr;
            }
        }

        // ----- O += P.V (P from S accumulators, split; V transposed) -----
        const uint32_t vb = sb + VBUF_OFF + buf * 34816;
        #pragma unroll
        for (int ks2 = 0; ks2 < 8; ks2++) {
            uint32_t pah[4], pal[4];
            #pragma unroll
            for (int t = 0; t < 2; t++)
                #pragma unroll
                for (int h2 = 0; h2 < 2; h2++)
                    split2(sf[2 * ks2 + t][h2 * 2], sf[2 * ks2 + t][h2 * 2 + 1],
                           pah[t * 2 + h2], pal[t * 2 + h2]);
            #pragma unroll
            for (int jj = 0; jj < 4; jj++) {
                uint32_t r4[4], l4[4];
                ldmx4(r4, vb + jj * 16 * VROWB + v_rofs + ks2 * 32);
                ldmx4(l4, vb + 17408 + jj * 16 * VROWB + v_rofs + ks2 * 32);
                uint32_t b0h[2] = {r4[0], r4[1]}, b1h[2] = {r4[2], r4[3]};
                uint32_t b0l[2] = {l4[0], l4[1]}, b1l[2] = {l4[2], l4[3]};
                mma16816(o[2 * jj],     pah, b0h);
                mma16816(o[2 * jj],     pah, b0l);
                mma16816(o[2 * jj],     pal, b0h);
                mma16816(o[2 * jj + 1], pah, b1h);
                mma16816(o[2 * jj + 1], pah, b1l);
                mma16816(o[2 * jj + 1], pal, b1h);
            }
        }
        __syncthreads();
    }

    // ----- epilogue: normalize + split-write into X slot 0 -----
    const int b = bhi >> 4, h = bhi & 15;
    const int r = lane >> 2, c2 = (lane & 3) * 2;
    #pragma unroll
    for (int h2 = 0; h2 < 2; h2++) {
        const int row = b * S + q0 + wid * 16 + r + h2 * 8;
        const float inv = 1.f / lrow[h2];
        #pragma unroll
        for (int j = 0; j < 8; j++) {
            const int col = h * 64 + j * 8 + c2;
            uint32_t hi, lo;
            split2(o[j][h2 * 2] * inv, o[j][h2 * 2 + 1] * inv, hi, lo);
            const size_t idx = (size_t)row * D + col;
            ((uint32_t*)g_Xh)[idx >> 1] = hi;
            ((uint32_t*)g_Xl)[idx >> 1] = lo;
        }
    }
}

// ---------------------------------------------------------------------------
extern "C" void kernel_launch(void* const* d_in, const int* in_sizes, int n_in,
                              void* d_out, int out_size)
{
    const float* q  = (const float*)d_in[0];
    const float* k  = (const float*)d_in[1];
    const float* v  = (const float*)d_in[2];
    const float* wq = (const float*)d_in[3];
    const float* wk = (const float*)d_in[4];
    const float* wv = (const float*)d_in[5];
    const float* wo = (const float*)d_in[6];
    float* out = (float*)d_out;

    cudaFuncSetAttribute(gemm_mma, cudaFuncAttributeMaxDynamicSharedMemorySize,
                         GEMM_SMEM);
    cudaFuncSetAttribute(attn_mma, cudaFuncAttributeMaxDynamicSharedMemorySize,
                         ATT_SMEM);

    // one fused split pass for all 7 inputs
    dim3 cb(256);
    dim3 cvg((M * D / 4 + 255) / 256, 7);        // (4096, 7)
    cvt_all<<<cvg, cb>>>((const float4*)q,  (const float4*)k,
                         (const float4*)v,  (const float4*)wq,
                         (const float4*)wk, (const float4*)wv,
                         (const float4*)wo);

    // fused Q/K/V projections
    gemm_mma<<<dim3(D / 128, M / 128, 3), cb, GEMM_SMEM>>>(nullptr, 1);

    // attention -> writes X slot 0
    attn_mma<<<dim3(16, BH), cb, ATT_SMEM>>>();

    // output projection
    gemm_mma<<<dim3(D / 128, M / 128, 1), cb, GEMM_SMEM>>>(out, 0);
}

// round 14
// speedup vs baseline: 3.2464x; 1.0329x over previous
#include <cuda_runtime.h>
#include <cuda_bf16.h>
#include <math.h>
#include <stdint.h>

// Problem constants
constexpr int B  = 2;
constexpr int S  = 2048;
constexpr int D  = 1024;
constexpr int H  = 16;
constexpr int HD = 64;
constexpr int M  = B * S;       // 4096
constexpr int BH = B * H;       // 32

// ---------------------------------------------------------------------------
// Scratch (__device__ globals) — bf16 hi/lo split pairs.
// X: 3 slots (q,k,v inputs; slot 0 reused for attention output).
// W: 4 slots (wq,wk,wv,wo).
// ---------------------------------------------------------------------------
__device__ __nv_bfloat16 g_Xh[3 * M * D],  g_Xl[3 * M * D];
__device__ __nv_bfloat16 g_Wh[4 * D * D],  g_Wl[4 * D * D];
__device__ __nv_bfloat16 g_Qh[BH * S * HD], g_Ql[BH * S * HD];   // [bh][s][hd]
__device__ __nv_bfloat16 g_Kh[BH * S * HD], g_Kl[BH * S * HD];   // [bh][s][hd]
__device__ __nv_bfloat16 g_Vth[BH * HD * S], g_Vtl[BH * HD * S]; // [bh][hd][s]

// ---------------------------------------------------------------------------
// PTX helpers (sm_80+ — valid on target sm_100)
// ---------------------------------------------------------------------------
__device__ __forceinline__ uint32_t smem_u32(const void* p) {
    uint32_t a;
    asm("{ .reg .u64 t; cvta.to.shared.u64 t, %1; cvt.u32.u64 %0, t; }"
        : "=r"(a) : "l"(p));
    return a;
}

__device__ __forceinline__ void ldmx4(uint32_t* r, uint32_t addr) {
    asm volatile("ldmatrix.sync.aligned.m8n8.x4.shared.b16 {%0,%1,%2,%3}, [%4];"
                 : "=r"(r[0]), "=r"(r[1]), "=r"(r[2]), "=r"(r[3]) : "r"(addr));
}

__device__ __forceinline__ void mma16816(float* d, const uint32_t* a,
                                         const uint32_t* b) {
    asm volatile(
        "mma.sync.aligned.m16n8k16.row.col.f32.bf16.bf16.f32 "
        "{%0,%1,%2,%3}, {%4,%5,%6,%7}, {%8,%9}, {%0,%1,%2,%3};"
        : "+f"(d[0]), "+f"(d[1]), "+f"(d[2]), "+f"(d[3])
        : "r"(a[0]), "r"(a[1]), "r"(a[2]), "r"(a[3]), "r"(b[0]), "r"(b[1]));
}

__device__ __forceinline__ void cp16(uint32_t saddr, const void* g) {
    asm volatile("cp.async.cg.shared.global [%0], [%1], 16;"
                 :: "r"(saddr), "l"(g));
}
#define CP_COMMIT() asm volatile("cp.async.commit_group;" ::: "memory")
#define CP_WAIT0()  asm volatile("cp.async.wait_group 0;" ::: "memory")

// fp32 pair -> (bf16x2 hi trunc, bf16x2 lo residual)
__device__ __forceinline__ void split2(float f0, float f1,
                                       uint32_t& hi, uint32_t& lo) {
    uint32_t u0 = __float_as_uint(f0), u1 = __float_as_uint(f1);
    hi = __byte_perm(u0, u1, 0x7632);
    float h0 = __uint_as_float(u0 & 0xFFFF0000u);
    float h1 = __uint_as_float(u1 & 0xFFFF0000u);
    __nv_bfloat162 l = __float22bfloat162_rn(make_float2(f0 - h0, f1 - h1));
    lo = *reinterpret_cast<uint32_t*>(&l);
}
__device__ __forceinline__ void split1(float f, __nv_bfloat16& hi,
                                       __nv_bfloat16& lo) {
    uint32_t u = __float_as_uint(f);
    __nv_bfloat16_raw hr; hr.x = (unsigned short)(u >> 16);
    hi = hr;
    float hf = __uint_as_float(u & 0xFFFF0000u);
    lo = __float2bfloat16_rn(f - hf);
}

// ---------------------------------------------------------------------------
// Fused fp32 -> bf16 hi/lo split for all 7 inputs in ONE launch.
// blockIdx.y: 0..2 -> X slots 0..2 (q,k,v), 3..6 -> W slots 0..3 (wq,wk,wv,wo)
// ---------------------------------------------------------------------------
__global__ __launch_bounds__(256)
void cvt_all(const float4* __restrict__ q,  const float4* __restrict__ k,
             const float4* __restrict__ v,  const float4* __restrict__ wq,
             const float4* __restrict__ wk, const float4* __restrict__ wv,
             const float4* __restrict__ wo)
{
    const int which = blockIdx.y;
    const int i = blockIdx.x * blockDim.x + threadIdx.x;
    const float4* src;
    uint2 *hi, *lo;
    int nvec;
    if (which < 3) {
        src = (which == 0) ? q : (which == 1) ? k : v;
        hi = (uint2*)g_Xh + (size_t)which * (M * D / 4);
        lo = (uint2*)g_Xl + (size_t)which * (M * D / 4);
        nvec = M * D / 4;
    } else {
        const int ws = which - 3;
        src = (ws == 0) ? wq : (ws == 1) ? wk : (ws == 2) ? wv : wo;
        hi = (uint2*)g_Wh + (size_t)ws * (D * D / 4);
        lo = (uint2*)g_Wl + (size_t)ws * (D * D / 4);
        nvec = D * D / 4;
    }
    if (i >= nvec) return;
    float4 x = src[i];
    uint2 h, l;
    split2(x.x, x.y, h.x, l.x);
    split2(x.z, x.w, h.y, l.y);
    hi[i] = h;
    lo[i] = l;
}

// ---------------------------------------------------------------------------
// mma.sync GEMM: C = X @ W^T, 128x128 CTA tile, 8 warps 64x32.
// K-chunk 32 + cp.async double-buffer -> 80KB smem -> 2 CTAs/SM.
// ---------------------------------------------------------------------------
constexpr int GROWB = 80;                  // 32 data halves + 8 pad
constexpr int GTILE = 128 * GROWB;         // 10240 B
constexpr int GBUF  = 4 * GTILE;           // Xh,Xl,Wh,Wl = 40960 B
constexpr int GEMM_SMEM = 2 * GBUF;        // 81920 B -> 2 CTAs/SM

__global__ __launch_bounds__(256, 2)
void gemm_mma(float* __restrict__ Out, int omode)
{
    extern __shared__ __align__(128) char smem[];
    const uint32_t sb = smem_u32(smem);
    const int tid  = threadIdx.x;
    const int lane = tid & 31;
    const int wid  = tid >> 5;
    const int wm   = wid >> 2;
    const int wn   = wid & 3;
    const int col0 = blockIdx.x * 128;
    const int row0 = blockIdx.y * 128;
    const int z    = blockIdx.z;

    int xs, ws, mode;
    float scale;
    if (omode == 0) { xs = 0; ws = 3; scale = 1.0f;  mode = 0; }
    else            { xs = z; ws = z; scale = (z == 0) ? 0.125f : 1.0f; mode = 1 + z; }

    const __nv_bfloat16* srcs[4] = {
        g_Xh + (size_t)xs * M * D + (size_t)row0 * D,
        g_Xl + (size_t)xs * M * D + (size_t)row0 * D,
        g_Wh + (size_t)ws * D * D + (size_t)col0 * D,
        g_Wl + (size_t)ws * D * D + (size_t)col0 * D };

    auto load_chunk = [&](int kt, int buf) {
        const uint32_t bs = sb + buf * GBUF;
        const int kbytes = kt * 64;        // 32 halves per chunk
        #pragma unroll
        for (int t = 0; t < 4; t++) {
            const char* g = (const char*)srcs[t] + kbytes;
            const uint32_t sd = bs + t * GTILE;
            #pragma unroll
            for (int p = 0; p < 2; p++) {
                int u = tid + p * 256;
                int r = u >> 2, c16 = (u & 3) * 16;
                cp16(sd + r * GROWB + c16, g + (size_t)r * 2048 + c16);
            }
        }
    };

    float c[4][4][4] = {};

    load_chunk(0, 0);
    CP_COMMIT();
    CP_WAIT0();
    __syncthreads();

    for (int kt = 0; kt < 32; kt++) {
        const int buf = kt & 1;
        if (kt < 31) { load_chunk(kt + 1, buf ^ 1); CP_COMMIT(); }

        const uint32_t base = sb + buf * GBUF;
        #pragma unroll
        for (int ks = 0; ks < 2; ks++) {
            const int k0 = ks * 16;
            uint32_t ah[4][4], al[4][4];
            {
                const uint32_t rofs = (uint32_t)(wm * 64 + (lane & 15)) * GROWB
                                    + (uint32_t)(k0 + (lane >> 4) * 8) * 2;
                #pragma unroll
                for (int i = 0; i < 4; i++) {
                    ldmx4(ah[i], base + 0 * GTILE + rofs + i * 16 * GROWB);
                    ldmx4(al[i], base + 1 * GTILE + rofs + i * 16 * GROWB);
                }
            }
            uint32_t bh[4][2], bl[4][2];
            {
                const uint32_t rpart = (uint32_t)(wn * 32 + (lane >> 4) * 8
                                                  + (lane & 7)) * GROWB
                                     + (uint32_t)(k0 + ((lane >> 3) & 1) * 8) * 2;
                #pragma unroll
                for (int pr = 0; pr < 2; pr++) {
                    uint32_t r4[4];
                    ldmx4(r4, base + 2 * GTILE + rpart + pr * 16 * GROWB);
                    bh[pr * 2 + 0][0] = r4[0]; bh[pr * 2 + 0][1] = r4[1];
                    bh[pr * 2 + 1][0] = r4[2]; bh[pr * 2 + 1][1] = r4[3];
                    ldmx4(r4, base + 3 * GTILE + rpart + pr * 16 * GROWB);
                    bl[pr * 2 + 0][0] = r4[0]; bl[pr * 2 + 0][1] = r4[1];
                    bl[pr * 2 + 1][0] = r4[2]; bl[pr * 2 + 1][1] = r4[3];
                }
            }
            #pragma unroll
            for (int i = 0; i < 4; i++)
                #pragma unroll
                for (int j = 0; j < 4; j++) {
                    mma16816(c[i][j], ah[i], bh[j]);
                    mma16816(c[i][j], ah[i], bl[j]);
                    mma16816(c[i][j], al[i], bh[j]);
                }
        }
        if (kt < 31) CP_WAIT0();
        __syncthreads();
    }

    // Epilogue
    const int g = lane >> 2, t2 = (lane & 3) * 2;
    #pragma unroll
    for (int i = 0; i < 4; i++) {
        #pragma unroll
        for (int half = 0; half < 2; half++) {
            const int gr = row0 + wm * 64 + i * 16 + g + half * 8;
            #pragma unroll
            for (int j = 0; j < 4; j++) {
                const int gc = col0 + wn * 32 + j * 8 + t2;
                float f0 = c[i][j][half * 2 + 0] * scale;
                float f1 = c[i][j][half * 2 + 1] * scale;
                if (mode == 0) {
                    *(float2*)&Out[(size_t)gr * D + gc] = make_float2(f0, f1);
                } else {
                    const int b = gr >> 11, s_ = gr & (S - 1);
                    const int h = gc >> 6, hd = gc & 63;
                    if (mode == 3) {   // transposed V
                        const size_t rb = (size_t)(b * H + h) * HD;
                        __nv_bfloat16 hi, lo;
                        split1(f0, hi, lo);
                        g_Vth[(rb + hd) * S + s_] = hi;
                        g_Vtl[(rb + hd) * S + s_] = lo;
                        split1(f1, hi, lo);
                        g_Vth[(rb + hd + 1) * S + s_] = hi;
                        g_Vtl[(rb + hd + 1) * S + s_] = lo;
                    } else {
                        __nv_bfloat16* dh = (mode == 1) ? g_Qh : g_Kh;
                        __nv_bfloat16* dl = (mode == 1) ? g_Ql : g_Kl;
                        const size_t idx = (((size_t)(b * H + h) * S) + s_) * HD + hd;
                        uint32_t hi, lo;
                        split2(f0, f1, hi, lo);
                        ((uint32_t*)dh)[idx >> 1] = hi;
                        ((uint32_t*)dl)[idx >> 1] = lo;
                    }
                }
            }
        }
    }
}

// ---------------------------------------------------------------------------
// Tensor-core flash attention — R11 structure, K/V/Q staging via cp.async.
// ---------------------------------------------------------------------------
constexpr int TROWB   = 144;
constexpr int VROWB   = 272;                       // 128 halves + 8 pad
constexpr int QH_OFF  = 0;
constexpr int QL_OFF  = 18432;                     // 128*144
constexpr int KBUF_OFF = 36864;                    // 2 bufs, stride 36864 (Kh,Kl)
constexpr int VBUF_OFF = 110592;                   // 2 bufs, stride 34816 (Vh,Vl)
constexpr int ATT_SMEM = 180224;

__global__ __launch_bounds__(256, 1)
void attn_mma()
{
    extern __shared__ __align__(128) char smem[];
    const uint32_t sb = smem_u32(smem);
    const int tid  = threadIdx.x;
    const int lane = tid & 31;
    const int wid  = tid >> 5;
    const int qt   = 15 - (int)blockIdx.x;     // heavy q-tiles first
    const int bhi  = blockIdx.y;
    const int q0   = qt * 128;

    const char* Qhp = (const char*)(g_Qh + (size_t)bhi * S * HD) + (size_t)q0 * 128;
    const char* Qlp = (const char*)(g_Ql + (size_t)bhi * S * HD) + (size_t)q0 * 128;
    const char* Khp = (const char*)(g_Kh + (size_t)bhi * S * HD);
    const char* Klp = (const char*)(g_Kl + (size_t)bhi * S * HD);
    const char* Vhp = (const char*)(g_Vth + (size_t)bhi * HD * S);
    const char* Vlp = (const char*)(g_Vtl + (size_t)bhi * HD * S);

    // Q tiles (once): 128 rows x 128B, hi+lo — cp.async
    #pragma unroll
    for (int p = 0; p < 4; p++) {
        int u = tid + p * 256;
        int r = u >> 3, c16 = (u & 7) * 16;
        cp16(sb + QH_OFF + r * TROWB + c16, Qhp + (size_t)r * 128 + c16);
        cp16(sb + QL_OFF + r * TROWB + c16, Qlp + (size_t)r * 128 + c16);
    }

    auto loadKV = [&](int kt, int buf) {
        const uint32_t kb = sb + KBUF_OFF + buf * 36864;
        const uint32_t vb = sb + VBUF_OFF + buf * 34816;
        const size_t kbyte = (size_t)kt * 128 * 128;   // K row offset (bytes)
        const size_t vbyte = (size_t)kt * 128 * 2;     // V col offset (bytes)
        #pragma unroll
        for (int p = 0; p < 4; p++) {
            int u = tid + p * 256;
            int r = u >> 3, c16 = (u & 7) * 16;
            cp16(kb + r * TROWB + c16,         Khp + kbyte + (size_t)r * 128 + c16);
            cp16(kb + 18432 + r * TROWB + c16, Klp + kbyte + (size_t)r * 128 + c16);
            int rv = u >> 4, cv = (u & 15) * 16;
            cp16(vb + rv * VROWB + cv,         Vhp + (size_t)rv * (S * 2) + vbyte + cv);
            cp16(vb + 17408 + rv * VROWB + cv, Vlp + (size_t)rv * (S * 2) + vbyte + cv);
        }
    };

    loadKV(0, 0);
    CP_COMMIT();
    CP_WAIT0();
    __syncthreads();

    float o[8][4] = {};
    float mrow[2] = {-1e30f, -1e30f}, lrow[2] = {0.f, 0.f};

    const uint32_t a_rofs = (uint32_t)(wid * 16 + (lane & 15)) * TROWB
                          + (uint32_t)((lane >> 4) * 8) * 2;
    const uint32_t b_rofs = (uint32_t)((lane >> 4) * 8 + (lane & 7)) * TROWB
                          + (uint32_t)(((lane >> 3) & 1) * 8) * 2;
    const uint32_t v_rofs = (uint32_t)((lane >> 4) * 8 + (lane & 7)) * VROWB
                          + (uint32_t)(((lane >> 3) & 1) * 8) * 2;

    for (int kt = 0; kt <= qt; kt++) {
        const int buf = kt & 1;
        if (kt < qt) { loadKV(kt + 1, buf ^ 1); CP_COMMIT(); }

        // ----- S = Q.K^T (fp32 accum, 3-way split) -----
        float sf[16][4] = {};
        const uint32_t kb = sb + KBUF_OFF + buf * 36864;
        #pragma unroll
        for (int ks = 0; ks < 4; ks++) {
            uint32_t ah[4], al[4];
            ldmx4(ah, sb + QH_OFF + a_rofs + ks * 32);
            ldmx4(al, sb + QL_OFF + a_rofs + ks * 32);
            #pragma unroll
            for (int jj = 0; jj < 8; jj++) {
                uint32_t r4[4], l4[4];
                ldmx4(r4, kb + jj * 16 * TROWB + b_rofs + ks * 32);
                ldmx4(l4, kb + 18432 + jj * 16 * TROWB + b_rofs + ks * 32);
                uint32_t b0h[2] = {r4[0], r4[1]}, b1h[2] = {r4[2], r4[3]};
                uint32_t b0l[2] = {l4[0], l4[1]}, b1l[2] = {l4[2], l4[3]};
                mma16816(sf[2 * jj],     ah, b0h);
                mma16816(sf[2 * jj],     ah, b0l);
                mma16816(sf[2 * jj],     al, b0h);
                mma16816(sf[2 * jj + 1], ah, b1h);
                mma16816(sf[2 * jj + 1], ah, b1l);
                mma16816(sf[2 * jj + 1], al, b1h);
            }
        }

        // ----- causal mask on diagonal tile -----
        if (kt == qt) {
            const int rb = wid * 16 + (lane >> 2);
            const int cb = (lane & 3) * 2;
            #pragma unroll
            for (int j = 0; j < 16; j++)
                #pragma unroll
                for (int e = 0; e < 4; e++) {
                    int row = rb + (e >> 1) * 8;
                    int col = j * 8 + cb + (e & 1);
                    if (col > row) sf[j][e] = -1e30f;
                }
        }

        // ----- online softmax (rows live in 4-lane quads) -----
        #pragma unroll
        for (int h2 = 0; h2 < 2; h2++) {
            float mx = -1e30f;
            #pragma unroll
            for (int j = 0; j < 16; j++)
                mx = fmaxf(mx, fmaxf(sf[j][h2 * 2], sf[j][h2 * 2 + 1]));
            mx = fmaxf(mx, __shfl_xor_sync(0xffffffffu, mx, 1));
            mx = fmaxf(mx, __shfl_xor_sync(0xffffffffu, mx, 2));
            const float mn   = fmaxf(mrow[h2], mx);
            const float corr = __expf(mrow[h2] - mn);
            float rs = 0.f;
            #pragma unroll
            for (int j = 0; j < 16; j++) {
                sf[j][h2 * 2]     = __expf(sf[j][h2 * 2]     - mn);
                sf[j][h2 * 2 + 1] = __expf(sf[j][h2 * 2 + 1] - mn);
                rs += sf[j][h2 * 2] + sf[j][h2 * 2 + 1];
            }
            rs += __shfl_xor_sync(0xffffffffu, rs, 1);
            rs += __shfl_xor_sync(0xffffffffu, rs, 2);
            lrow[h2] = lrow[h2] * corr + rs;
            mrow[h2] = mn;
            #pragma unroll
            for (int j = 0; j < 8; j++) {
                o[j][h2 * 2]     *= corr;
                o[j][h2 * 2 + 1] *= corr;
            }
        }

        // ----- O += P.V (P from S accumulators, split; V transposed) -----
        const uint32_t vb = sb + VBUF_OFF + buf * 34816;
        #pragma unroll
        for (int ks2 = 0; ks2 < 8; ks2++) {
            uint32_t pah[4], pal[4];
            #pragma unroll
            for (int t = 0; t < 2; t++)
                #pragma unroll
                for (int h2 = 0; h2 < 2; h2++)
                    split2(sf[2 * ks2 + t][h2 * 2], sf[2 * ks2 + t][h2 * 2 + 1],
                           pah[t * 2 + h2], pal[t * 2 + h2]);
            #pragma unroll
            for (int jj = 0; jj < 4; jj++) {
                uint32_t r4[4], l4[4];
                ldmx4(r4, vb + jj * 16 * VROWB + v_rofs + ks2 * 32);
                ldmx4(l4, vb + 17408 + jj * 16 * VROWB + v_rofs + ks2 * 32);
                uint32_t b0h[2] = {r4[0], r4[1]}, b1h[2] = {r4[2], r4[3]};
                uint32_t b0l[2] = {l4[0], l4[1]}, b1l[2] = {l4[2], l4[3]};
                mma16816(o[2 * jj],     pah, b0h);
                mma16816(o[2 * jj],     pah, b0l);
                mma16816(o[2 * jj],     pal, b0h);
                mma16816(o[2 * jj + 1], pah, b1h);
                mma16816(o[2 * jj + 1], pah, b1l);
                mma16816(o[2 * jj + 1], pal, b1h);
            }
        }
        if (kt < qt) CP_WAIT0();
        __syncthreads();
    }

    // ----- epilogue: normalize + split-write into X slot 0 -----
    const int b = bhi >> 4, h = bhi & 15;
    const int r = lane >> 2, c2 = (lane & 3) * 2;
    #pragma unroll
    for (int h2 = 0; h2 < 2; h2++) {
        const int row = b * S + q0 + wid * 16 + r + h2 * 8;
        const float inv = 1.f / lrow[h2];
        #pragma unroll
        for (int j = 0; j < 8; j++) {
            const int col = h * 64 + j * 8 + c2;
            uint32_t hi, lo;
            split2(o[j][h2 * 2] * inv, o[j][h2 * 2 + 1] * inv, hi, lo);
            const size_t idx = (size_t)row * D + col;
            ((uint32_t*)g_Xh)[idx >> 1] = hi;
            ((uint32_t*)g_Xl)[idx >> 1] = lo;
        }
    }
}

// ---------------------------------------------------------------------------
extern "C" void kernel_launch(void* const* d_in, const int* in_sizes, int n_in,
                              void* d_out, int out_size)
{
    const float* q  = (const float*)d_in[0];
    const float* k  = (const float*)d_in[1];
    const float* v  = (const float*)d_in[2];
    const float* wq = (const float*)d_in[3];
    const float* wk = (const float*)d_in[4];
    const float* wv = (const float*)d_in[5];
    const float* wo = (const float*)d_in[6];
    float* out = (float*)d_out;

    cudaFuncSetAttribute(gemm_mma, cudaFuncAttributeMaxDynamicSharedMemorySize,
                         GEMM_SMEM);
    cudaFuncSetAttribute(attn_mma, cudaFuncAttributeMaxDynamicSharedMemorySize,
                         ATT_SMEM);

    // one fused split pass for all 7 inputs
    dim3 cb(256);
    dim3 cvg((M * D / 4 + 255) / 256, 7);        // (4096, 7)
    cvt_all<<<cvg, cb>>>((const float4*)q,  (const float4*)k,
                         (const float4*)v,  (const float4*)wq,
                         (const float4*)wk, (const float4*)wv,
                         (const float4*)wo);

    // fused Q/K/V projections
    gemm_mma<<<dim3(D / 128, M / 128, 3), cb, GEMM_SMEM>>>(nullptr, 1);

    // attention -> writes X slot 0
    attn_mma<<<dim3(16, BH), cb, ATT_SMEM>>>();

    // output projection
    gemm_mma<<<dim3(D / 128, M / 128, 1), cb, GEMM_SMEM>>>(out, 0);
}